// round 1
// baseline (speedup 1.0000x reference)
#include <cuda_runtime.h>

#define N_NODES 50000
#define N_EDGES 800000
#define IN_F    512
#define HD      256
#define NH      4

// ---------------- scratch (static __device__ — no allocation) ----------------
__device__ float g_ft[N_NODES * HD];
__device__ float g_el[N_NODES * NH];
__device__ float g_er[N_NODES * NH];
__device__ int   g_deg[N_NODES];
__device__ int   g_cursor[N_NODES];
__device__ int   g_row_start[N_NODES + 1];
__device__ int   g_csr_src[N_EDGES];

// ---------------- GEMM: g_ft = feat[50000,512] @ W[512,256] ------------------
#define BM 128
#define BN 128
#define BK 16

__global__ __launch_bounds__(256, 2)
void sgemm_kernel(const float* __restrict__ A, const float* __restrict__ B) {
    __shared__ float As[BK][BM + 4];
    __shared__ float Bs[BK][BN + 4];
    const int tid  = threadIdx.x;
    const int row0 = blockIdx.y * BM;
    const int col0 = blockIdx.x * BN;

    const int a_row = tid >> 2;          // 0..63
    const int a_k   = (tid & 3) * 4;     // 0,4,8,12
    const int b_row = tid >> 5;          // 0..7
    const int b_col = (tid & 31) * 4;    // 0..124

    const int tx = tid & 15, ty = tid >> 4;
    const int rm = ty * 8, cn = tx * 8;

    unsigned long long acc[8][4];
#pragma unroll
    for (int i = 0; i < 8; i++)
#pragma unroll
        for (int j = 0; j < 4; j++) acc[i][j] = 0ULL;

    for (int kt = 0; kt < IN_F; kt += BK) {
        // A tile (transposed into smem), zero-padded past N_NODES
#pragma unroll
        for (int r = 0; r < 2; r++) {
            int row = row0 + a_row + r * 64;
            float4 v = make_float4(0.f, 0.f, 0.f, 0.f);
            if (row < N_NODES)
                v = *reinterpret_cast<const float4*>(A + (long)row * IN_F + kt + a_k);
            As[a_k + 0][a_row + r * 64] = v.x;
            As[a_k + 1][a_row + r * 64] = v.y;
            As[a_k + 2][a_row + r * 64] = v.z;
            As[a_k + 3][a_row + r * 64] = v.w;
        }
        // B tile
#pragma unroll
        for (int r = 0; r < 2; r++) {
            int krow = kt + b_row + r * 8;
            float4 v = *reinterpret_cast<const float4*>(B + krow * HD + col0 + b_col);
            *reinterpret_cast<float4*>(&Bs[b_row + r * 8][b_col]) = v;
        }
        __syncthreads();

#pragma unroll
        for (int kk = 0; kk < BK; kk++) {
            float a[8];
#pragma unroll
            for (int i = 0; i < 8; i++) a[i] = As[kk][rm + i];
            unsigned long long b2[4];
#pragma unroll
            for (int j = 0; j < 4; j++)
                b2[j] = *reinterpret_cast<const unsigned long long*>(&Bs[kk][cn + 2 * j]);
#pragma unroll
            for (int i = 0; i < 8; i++) {
                unsigned long long aa;
                asm("mov.b64 %0, {%1, %1};" : "=l"(aa) : "f"(a[i]));
#pragma unroll
                for (int j = 0; j < 4; j++)
                    asm("fma.rn.f32x2 %0, %1, %2, %0;"
                        : "+l"(acc[i][j]) : "l"(aa), "l"(b2[j]));
            }
        }
        __syncthreads();
    }

#pragma unroll
    for (int i = 0; i < 8; i++) {
        int row = row0 + rm + i;
        if (row >= N_NODES) continue;
        float v[8];
#pragma unroll
        for (int j = 0; j < 4; j++)
            asm("mov.b64 {%0, %1}, %2;" : "=f"(v[2 * j]), "=f"(v[2 * j + 1]) : "l"(acc[i][j]));
        float4* p = reinterpret_cast<float4*>(g_ft + (long)row * HD + col0 + cn);
        p[0] = make_float4(v[0], v[1], v[2], v[3]);
        p[1] = make_float4(v[4], v[5], v[6], v[7]);
    }
}

// ---------------- el/er: per-node attention logits ----------------------------
// One warp per node. lane covers 8 contiguous features; head = lane>>3.
__global__ void elr_kernel(const float* __restrict__ al, const float* __restrict__ ar) {
    int w    = (blockIdx.x * blockDim.x + threadIdx.x) >> 5;
    int lane = threadIdx.x & 31;
    if (w >= N_NODES) return;
    const float4* fp = reinterpret_cast<const float4*>(g_ft + (long)w * HD + lane * 8);
    float4 f0 = fp[0], f1 = fp[1];
    const float4* lp = reinterpret_cast<const float4*>(al + lane * 8);
    const float4* rp = reinterpret_cast<const float4*>(ar + lane * 8);
    float4 l0 = lp[0], l1 = lp[1];
    float4 r0 = rp[0], r1 = rp[1];
    float pl = f0.x*l0.x + f0.y*l0.y + f0.z*l0.z + f0.w*l0.w
             + f1.x*l1.x + f1.y*l1.y + f1.z*l1.z + f1.w*l1.w;
    float pr = f0.x*r0.x + f0.y*r0.y + f0.z*r0.z + f0.w*r0.w
             + f1.x*r1.x + f1.y*r1.y + f1.z*r1.z + f1.w*r1.w;
#pragma unroll
    for (int off = 1; off < 8; off <<= 1) {
        pl += __shfl_xor_sync(0xffffffffu, pl, off);
        pr += __shfl_xor_sync(0xffffffffu, pr, off);
    }
    if ((lane & 7) == 0) {
        g_el[w * NH + (lane >> 3)] = pl;
        g_er[w * NH + (lane >> 3)] = pr;
    }
}

// ---------------- CSR build ---------------------------------------------------
__global__ void zero_kernel() {
    int i = blockIdx.x * blockDim.x + threadIdx.x;
    if (i < N_NODES) { g_deg[i] = 0; g_cursor[i] = 0; }
}

__global__ void hist_kernel(const int* __restrict__ dst) {
    int i = blockIdx.x * blockDim.x + threadIdx.x;
    if (i < N_EDGES) atomicAdd(&g_deg[dst[i]], 1);
}

__global__ void scan_kernel() {
    __shared__ int sums[1024];
    int tid = threadIdx.x;
    const int chunk = (N_NODES + 1023) / 1024;  // 49
    int lo = tid * chunk;
    int hi = lo + chunk; if (hi > N_NODES) hi = N_NODES;
    int s = 0;
    for (int i = lo; i < hi; i++) s += g_deg[i];
    sums[tid] = s;
    __syncthreads();
    for (int off = 1; off < 1024; off <<= 1) {
        int v = (tid >= off) ? sums[tid - off] : 0;
        __syncthreads();
        sums[tid] += v;
        __syncthreads();
    }
    int base = (tid == 0) ? 0 : sums[tid - 1];
    for (int i = lo; i < hi; i++) { g_row_start[i] = base; base += g_deg[i]; }
    if (tid == 1023) g_row_start[N_NODES] = sums[1023];
}

__global__ void scatter_kernel(const int* __restrict__ src, const int* __restrict__ dst) {
    int i = blockIdx.x * blockDim.x + threadIdx.x;
    if (i < N_EDGES) {
        int v = dst[i];
        int pos = g_row_start[v] + atomicAdd(&g_cursor[v], 1);
        g_csr_src[pos] = src[i];
    }
}

// ---------------- aggregation: one warp per destination node ------------------
__global__ __launch_bounds__(256)
void aggregate_kernel(float* __restrict__ out) {
    int v    = (blockIdx.x * blockDim.x + threadIdx.x) >> 5;
    int lane = threadIdx.x & 31;
    if (v >= N_NODES) return;
    int start = g_row_start[v];
    int end   = g_row_start[v + 1];

    // ---- pass 1: online softmax stats. 8 edge slots x 4 heads per warp.
    int hh   = lane & 3;
    int slot = lane >> 2;
    float er_h = g_er[v * NH + hh];
    float m = -1e30f, ssum = 0.f;
    for (int e = start + slot; e < end; e += 8) {
        int s = g_csr_src[e];
        float x = g_el[s * NH + hh] + er_h;
        x = (x > 0.f) ? x : 0.2f * x;
        float mn = fmaxf(m, x);
        ssum = ssum * __expf(m - mn) + __expf(x - mn);
        m = mn;
    }
#pragma unroll
    for (int off = 4; off < 32; off <<= 1) {
        float m2 = __shfl_xor_sync(0xffffffffu, m, off);
        float s2 = __shfl_xor_sync(0xffffffffu, ssum, off);
        float mn = fmaxf(m, m2);
        ssum = ssum * __expf(m - mn) + s2 * __expf(m2 - mn);
        m = mn;
    }

    // ---- pass 2: weighted gather. lane covers 8 features; head = lane>>3.
    int hg = lane >> 3;
    float m_g  = __shfl_sync(0xffffffffu, m, hg);     // lane hg holds head hg
    float s_g  = __shfl_sync(0xffffffffu, ssum, hg);
    float er_g = __shfl_sync(0xffffffffu, er_h, hg);
    float inv = (s_g > 0.f) ? (1.0f / s_g) : 0.f;

    float acc[8];
#pragma unroll
    for (int k = 0; k < 8; k++) acc[k] = 0.f;

    for (int e = start; e < end; e++) {
        int s = g_csr_src[e];
        float x = g_el[s * NH + hg] + er_g;
        x = (x > 0.f) ? x : 0.2f * x;
        float wgt = __expf(x - m_g) * inv;
        const float4* p = reinterpret_cast<const float4*>(g_ft + (long)s * HD + lane * 8);
        float4 u0 = p[0], u1 = p[1];
        acc[0] = fmaf(wgt, u0.x, acc[0]);
        acc[1] = fmaf(wgt, u0.y, acc[1]);
        acc[2] = fmaf(wgt, u0.z, acc[2]);
        acc[3] = fmaf(wgt, u0.w, acc[3]);
        acc[4] = fmaf(wgt, u1.x, acc[4]);
        acc[5] = fmaf(wgt, u1.y, acc[5]);
        acc[6] = fmaf(wgt, u1.z, acc[6]);
        acc[7] = fmaf(wgt, u1.w, acc[7]);
    }
    float4* op = reinterpret_cast<float4*>(out + (long)v * HD + lane * 8);
    op[0] = make_float4(acc[0], acc[1], acc[2], acc[3]);
    op[1] = make_float4(acc[4], acc[5], acc[6], acc[7]);
}

// ---------------- launch ------------------------------------------------------
extern "C" void kernel_launch(void* const* d_in, const int* in_sizes, int n_in,
                              void* d_out, int out_size) {
    const float* feat = (const float*)d_in[0];
    const float* W    = (const float*)d_in[1];
    const float* al   = (const float*)d_in[2];
    const float* ar   = (const float*)d_in[3];
    const int*   src  = (const int*)d_in[4];
    const int*   dst  = (const int*)d_in[5];
    float* out = (float*)d_out;

    zero_kernel<<<(N_NODES + 255) / 256, 256>>>();

    dim3 gg(HD / BN, (N_NODES + BM - 1) / BM);
    sgemm_kernel<<<gg, 256>>>(feat, W);

    elr_kernel<<<(N_NODES * 32 + 255) / 256, 256>>>(al, ar);

    hist_kernel<<<(N_EDGES + 255) / 256, 256>>>(dst);
    scan_kernel<<<1, 1024>>>();
    scatter_kernel<<<(N_EDGES + 255) / 256, 256>>>(src, dst);

    aggregate_kernel<<<(N_NODES * 32 + 255) / 256, 256>>>(out);
}

// round 2
// speedup vs baseline: 1.0043x; 1.0043x over previous
#include <cuda_runtime.h>

#define N_NODES 50000
#define N_EDGES 800000
#define IN_F    512
#define HD      256
#define NH      4

// ---------------- scratch (static __device__ — no allocation) ----------------
__device__ float g_ft[N_NODES * HD];
__device__ float g_el[N_NODES * NH];
__device__ float g_er[N_NODES * NH];
__device__ int   g_deg[N_NODES];
__device__ int   g_cursor[N_NODES];
__device__ int   g_row_start[N_NODES + 1];
__device__ int   g_csr_src[N_EDGES];

// ---------------- GEMM: g_ft = feat[50000,512] @ W[512,256] ------------------
#define BM 128
#define BN 128
#define BK 16

__global__ __launch_bounds__(256, 2)
void sgemm_kernel(const float* __restrict__ A, const float* __restrict__ B) {
    __shared__ float As[BK][BM + 4];
    __shared__ float Bs[BK][BN + 4];
    const int tid  = threadIdx.x;
    const int row0 = blockIdx.y * BM;
    const int col0 = blockIdx.x * BN;

    const int a_row = tid >> 2;          // 0..63
    const int a_k   = (tid & 3) * 4;     // 0,4,8,12
    const int b_row = tid >> 5;          // 0..7
    const int b_col = (tid & 31) * 4;    // 0..124

    const int tx = tid & 15, ty = tid >> 4;
    const int rm = ty * 8, cn = tx * 8;

    unsigned long long acc[8][4];
#pragma unroll
    for (int i = 0; i < 8; i++)
#pragma unroll
        for (int j = 0; j < 4; j++) acc[i][j] = 0ULL;

    for (int kt = 0; kt < IN_F; kt += BK) {
        // A tile (transposed into smem), zero-padded past N_NODES
#pragma unroll
        for (int r = 0; r < 2; r++) {
            int row = row0 + a_row + r * 64;
            float4 v = make_float4(0.f, 0.f, 0.f, 0.f);
            if (row < N_NODES)
                v = *reinterpret_cast<const float4*>(A + (long)row * IN_F + kt + a_k);
            As[a_k + 0][a_row + r * 64] = v.x;
            As[a_k + 1][a_row + r * 64] = v.y;
            As[a_k + 2][a_row + r * 64] = v.z;
            As[a_k + 3][a_row + r * 64] = v.w;
        }
        // B tile
#pragma unroll
        for (int r = 0; r < 2; r++) {
            int krow = kt + b_row + r * 8;
            float4 v = *reinterpret_cast<const float4*>(B + krow * HD + col0 + b_col);
            *reinterpret_cast<float4*>(&Bs[b_row + r * 8][b_col]) = v;
        }
        __syncthreads();

#pragma unroll
        for (int kk = 0; kk < BK; kk++) {
            float a[8];
#pragma unroll
            for (int i = 0; i < 8; i++) a[i] = As[kk][rm + i];
            unsigned long long b2[4];
#pragma unroll
            for (int j = 0; j < 4; j++)
                b2[j] = *reinterpret_cast<const unsigned long long*>(&Bs[kk][cn + 2 * j]);
#pragma unroll
            for (int i = 0; i < 8; i++) {
                unsigned long long aa;
                asm("mov.b64 %0, {%1, %1};" : "=l"(aa) : "f"(a[i]));
#pragma unroll
                for (int j = 0; j < 4; j++)
                    asm("fma.rn.f32x2 %0, %1, %2, %0;"
                        : "+l"(acc[i][j]) : "l"(aa), "l"(b2[j]));
            }
        }
        __syncthreads();
    }

#pragma unroll
    for (int i = 0; i < 8; i++) {
        int row = row0 + rm + i;
        if (row >= N_NODES) continue;
        float v[8];
#pragma unroll
        for (int j = 0; j < 4; j++)
            asm("mov.b64 {%0, %1}, %2;" : "=f"(v[2 * j]), "=f"(v[2 * j + 1]) : "l"(acc[i][j]));
        float4* p = reinterpret_cast<float4*>(g_ft + (long)row * HD + col0 + cn);
        p[0] = make_float4(v[0], v[1], v[2], v[3]);
        p[1] = make_float4(v[4], v[5], v[6], v[7]);
    }
}

// ---------------- el/er: per-node attention logits ----------------------------
// One warp per node. lane covers 8 contiguous features; head = lane>>3.
__global__ void elr_kernel(const float* __restrict__ al, const float* __restrict__ ar) {
    int w    = (blockIdx.x * blockDim.x + threadIdx.x) >> 5;
    int lane = threadIdx.x & 31;
    if (w >= N_NODES) return;
    const float4* fp = reinterpret_cast<const float4*>(g_ft + (long)w * HD + lane * 8);
    float4 f0 = fp[0], f1 = fp[1];
    const float4* lp = reinterpret_cast<const float4*>(al + lane * 8);
    const float4* rp = reinterpret_cast<const float4*>(ar + lane * 8);
    float4 l0 = lp[0], l1 = lp[1];
    float4 r0 = rp[0], r1 = rp[1];
    float pl = f0.x*l0.x + f0.y*l0.y + f0.z*l0.z + f0.w*l0.w
             + f1.x*l1.x + f1.y*l1.y + f1.z*l1.z + f1.w*l1.w;
    float pr = f0.x*r0.x + f0.y*r0.y + f0.z*r0.z + f0.w*r0.w
             + f1.x*r1.x + f1.y*r1.y + f1.z*r1.z + f1.w*r1.w;
#pragma unroll
    for (int off = 1; off < 8; off <<= 1) {
        pl += __shfl_xor_sync(0xffffffffu, pl, off);
        pr += __shfl_xor_sync(0xffffffffu, pr, off);
    }
    if ((lane & 7) == 0) {
        g_el[w * NH + (lane >> 3)] = pl;
        g_er[w * NH + (lane >> 3)] = pr;
    }
}

// ---------------- CSR build ---------------------------------------------------
__global__ void zero_kernel() {
    int i = blockIdx.x * blockDim.x + threadIdx.x;
    if (i < N_NODES) { g_deg[i] = 0; g_cursor[i] = 0; }
}

__global__ void hist_kernel(const int* __restrict__ dst) {
    int i = blockIdx.x * blockDim.x + threadIdx.x;
    if (i < N_EDGES) atomicAdd(&g_deg[dst[i]], 1);
}

__global__ void scan_kernel() {
    __shared__ int sums[1024];
    int tid = threadIdx.x;
    const int chunk = (N_NODES + 1023) / 1024;  // 49
    int lo = tid * chunk;
    int hi = lo + chunk; if (hi > N_NODES) hi = N_NODES;
    int s = 0;
    for (int i = lo; i < hi; i++) s += g_deg[i];
    sums[tid] = s;
    __syncthreads();
    for (int off = 1; off < 1024; off <<= 1) {
        int v = (tid >= off) ? sums[tid - off] : 0;
        __syncthreads();
        sums[tid] += v;
        __syncthreads();
    }
    int base = (tid == 0) ? 0 : sums[tid - 1];
    for (int i = lo; i < hi; i++) { g_row_start[i] = base; base += g_deg[i]; }
    if (tid == 1023) g_row_start[N_NODES] = sums[1023];
}

__global__ void scatter_kernel(const int* __restrict__ src, const int* __restrict__ dst) {
    int i = blockIdx.x * blockDim.x + threadIdx.x;
    if (i < N_EDGES) {
        int v = dst[i];
        int pos = g_row_start[v] + atomicAdd(&g_cursor[v], 1);
        g_csr_src[pos] = src[i];
    }
}

// ---------------- aggregation: one warp per destination node ------------------
__global__ __launch_bounds__(256)
void aggregate_kernel(float* __restrict__ out) {
    int v    = (blockIdx.x * blockDim.x + threadIdx.x) >> 5;
    int lane = threadIdx.x & 31;
    if (v >= N_NODES) return;
    int start = g_row_start[v];
    int end   = g_row_start[v + 1];

    // ---- pass 1: online softmax stats. 8 edge slots x 4 heads per warp.
    int hh   = lane & 3;
    int slot = lane >> 2;
    float er_h = g_er[v * NH + hh];
    float m = -1e30f, ssum = 0.f;
    for (int e = start + slot; e < end; e += 8) {
        int s = g_csr_src[e];
        float x = g_el[s * NH + hh] + er_h;
        x = (x > 0.f) ? x : 0.2f * x;
        float mn = fmaxf(m, x);
        ssum = ssum * __expf(m - mn) + __expf(x - mn);
        m = mn;
    }
#pragma unroll
    for (int off = 4; off < 32; off <<= 1) {
        float m2 = __shfl_xor_sync(0xffffffffu, m, off);
        float s2 = __shfl_xor_sync(0xffffffffu, ssum, off);
        float mn = fmaxf(m, m2);
        ssum = ssum * __expf(m - mn) + s2 * __expf(m2 - mn);
        m = mn;
    }

    // ---- pass 2: weighted gather. lane covers 8 features; head = lane>>3.
    int hg = lane >> 3;
    float m_g  = __shfl_sync(0xffffffffu, m, hg);     // lane hg holds head hg
    float s_g  = __shfl_sync(0xffffffffu, ssum, hg);
    float er_g = __shfl_sync(0xffffffffu, er_h, hg);
    float inv = (s_g > 0.f) ? (1.0f / s_g) : 0.f;

    float acc[8];
#pragma unroll
    for (int k = 0; k < 8; k++) acc[k] = 0.f;

    for (int e = start; e < end; e++) {
        int s = g_csr_src[e];
        float x = g_el[s * NH + hg] + er_g;
        x = (x > 0.f) ? x : 0.2f * x;
        float wgt = __expf(x - m_g) * inv;
        const float4* p = reinterpret_cast<const float4*>(g_ft + (long)s * HD + lane * 8);
        float4 u0 = p[0], u1 = p[1];
        acc[0] = fmaf(wgt, u0.x, acc[0]);
        acc[1] = fmaf(wgt, u0.y, acc[1]);
        acc[2] = fmaf(wgt, u0.z, acc[2]);
        acc[3] = fmaf(wgt, u0.w, acc[3]);
        acc[4] = fmaf(wgt, u1.x, acc[4]);
        acc[5] = fmaf(wgt, u1.y, acc[5]);
        acc[6] = fmaf(wgt, u1.z, acc[6]);
        acc[7] = fmaf(wgt, u1.w, acc[7]);
    }
    float4* op = reinterpret_cast<float4*>(out + (long)v * HD + lane * 8);
    op[0] = make_float4(acc[0], acc[1], acc[2], acc[3]);
    op[1] = make_float4(acc[4], acc[5], acc[6], acc[7]);
}

// ---------------- launch ------------------------------------------------------
extern "C" void kernel_launch(void* const* d_in, const int* in_sizes, int n_in,
                              void* d_out, int out_size) {
    const float* feat = (const float*)d_in[0];
    const float* W    = (const float*)d_in[1];
    const float* al   = (const float*)d_in[2];
    const float* ar   = (const float*)d_in[3];
    const int*   src  = (const int*)d_in[4];
    const int*   dst  = (const int*)d_in[5];
    float* out = (float*)d_out;

    zero_kernel<<<(N_NODES + 255) / 256, 256>>>();

    dim3 gg(HD / BN, (N_NODES + BM - 1) / BM);
    sgemm_kernel<<<gg, 256>>>(feat, W);

    elr_kernel<<<(N_NODES * 32 + 255) / 256, 256>>>(al, ar);

    hist_kernel<<<(N_EDGES + 255) / 256, 256>>>(dst);
    scan_kernel<<<1, 1024>>>();
    scatter_kernel<<<(N_EDGES + 255) / 256, 256>>>(src, dst);

    aggregate_kernel<<<(N_NODES * 32 + 255) / 256, 256>>>(out);
}

// round 4
// speedup vs baseline: 1.4553x; 1.4491x over previous
#include <cuda_runtime.h>
#include <cuda_bf16.h>
#include <cstdint>

#define N_NODES 50000
#define N_EDGES 800000
#define IN_F    512
#define HD      256
#define NH      4

// ---------------- scratch (static __device__ — no allocation) ----------------
__device__ float g_ft[N_NODES * HD];
__device__ float g_el[N_NODES * NH];
__device__ float g_er[N_NODES * NH];
__device__ int   g_deg[N_NODES];
__device__ int   g_cursor[N_NODES];
__device__ int   g_row_start[N_NODES + 1];
__device__ int   g_csr_src[N_EDGES];
__device__ __nv_bfloat16 g_Whi[IN_F * HD];   // [K=512][N=256] row-major, hi part
__device__ __nv_bfloat16 g_Wlo[IN_F * HD];   // lo part

// ---------------- helpers ------------------------------------------------------
__device__ __forceinline__ uint32_t smem_u32(const void* p) {
    uint32_t a;
    asm("{ .reg .u64 t; cvta.to.shared.u64 t, %1; cvt.u32.u64 %0, t; }"
        : "=r"(a) : "l"(p));
    return a;
}

__device__ __forceinline__ void ldsm_x4(uint32_t* r, uint32_t addr) {
    asm volatile("ldmatrix.sync.aligned.m8n8.x4.shared.b16 {%0,%1,%2,%3}, [%4];"
                 : "=r"(r[0]), "=r"(r[1]), "=r"(r[2]), "=r"(r[3]) : "r"(addr));
}
__device__ __forceinline__ void ldsm_x4_t(uint32_t* r, uint32_t addr) {
    asm volatile("ldmatrix.sync.aligned.m8n8.x4.trans.shared.b16 {%0,%1,%2,%3}, [%4];"
                 : "=r"(r[0]), "=r"(r[1]), "=r"(r[2]), "=r"(r[3]) : "r"(addr));
}
__device__ __forceinline__ void mma16816(float* d, const uint32_t* a, const uint32_t* b) {
    asm volatile("mma.sync.aligned.m16n8k16.row.col.f32.bf16.bf16.f32 "
                 "{%0,%1,%2,%3}, {%4,%5,%6,%7}, {%8,%9}, {%0,%1,%2,%3};"
                 : "+f"(d[0]), "+f"(d[1]), "+f"(d[2]), "+f"(d[3])
                 : "r"(a[0]), "r"(a[1]), "r"(a[2]), "r"(a[3]), "r"(b[0]), "r"(b[1]));
}

__device__ __forceinline__ uint32_t pack_bf16x2(__nv_bfloat16 a, __nv_bfloat16 b) {
    __nv_bfloat162 p = __halves2bfloat162(a, b);
    return *reinterpret_cast<uint32_t*>(&p);
}

// ---------------- W split: g_Whi/g_Wlo[k][n] -----------------------------------
__global__ void wsplit_kernel(const float* __restrict__ W) {
    int i = blockIdx.x * blockDim.x + threadIdx.x;
    if (i >= IN_F * HD) return;
    float w = W[i];
    __nv_bfloat16 hi = __float2bfloat16(w);
    float r = w - __bfloat162float(hi);
    g_Whi[i] = hi;
    g_Wlo[i] = __float2bfloat16(r);
}

// ---------------- mma.sync GEMM: g_ft = feat @ W, fused el/er ------------------
// CTA: 512 threads (16 warps, 4x4), tile 64(M) x 256(N). K in 16 chunks of 32.
// Warp tile 16(M) x 64(N) -> warp_n == head index.
#define A_STRIDE 40    // bf16 elems per A smem row (32 + 8 pad)
#define B_STRIDE 264   // bf16 elems per B smem row (256 + 8 pad)

__global__ __launch_bounds__(512, 1)
void mma_gemm_kernel(const float* __restrict__ feat,
                     const float* __restrict__ al,
                     const float* __restrict__ ar) {
    __shared__ __nv_bfloat16 Ahi[64 * A_STRIDE];
    __shared__ __nv_bfloat16 Alo[64 * A_STRIDE];
    __shared__ __nv_bfloat16 Bhi[32 * B_STRIDE];
    __shared__ __nv_bfloat16 Blo[32 * B_STRIDE];

    const int tid    = threadIdx.x;
    const int lane   = tid & 31;
    const int wid    = tid >> 5;
    const int warp_m = wid & 3;    // 0..3 -> 16 rows each
    const int warp_n = wid >> 2;   // 0..3 -> head / 64 cols each
    const int row_base = blockIdx.x * 64;

    // gmem load mapping
    const int a_r = tid >> 3;            // 0..63
    const int a_c = (tid & 7) * 4;       // 0..28
    const int a_g = row_base + a_r;
    const int b_r = tid >> 4;            // 0..31
    const int b_c = (tid & 15) * 16;     // 0..240

    const uint32_t aHiB = smem_u32(Ahi);
    const uint32_t aLoB = smem_u32(Alo);
    const uint32_t bHiB = smem_u32(Bhi);
    const uint32_t bLoB = smem_u32(Blo);

    float acc[8][4];
#pragma unroll
    for (int nf = 0; nf < 8; nf++)
#pragma unroll
        for (int j = 0; j < 4; j++) acc[nf][j] = 0.f;

    float4 a_pf;
    uint4  bh_pf[2], bl_pf[2];

    // prologue: prefetch chunk 0
    {
        a_pf = make_float4(0.f, 0.f, 0.f, 0.f);
        if (a_g < N_NODES)
            a_pf = *reinterpret_cast<const float4*>(feat + (long)a_g * IN_F + a_c);
        const uint4* ph = reinterpret_cast<const uint4*>(g_Whi + b_r * HD + b_c);
        const uint4* pl = reinterpret_cast<const uint4*>(g_Wlo + b_r * HD + b_c);
        bh_pf[0] = ph[0]; bh_pf[1] = ph[1];
        bl_pf[0] = pl[0]; bl_pf[1] = pl[1];
    }

    for (int c = 0; c < 16; c++) {
        // ---- store prefetched chunk into smem ----
        {
            __nv_bfloat16 h0 = __float2bfloat16(a_pf.x);
            __nv_bfloat16 h1 = __float2bfloat16(a_pf.y);
            __nv_bfloat16 h2 = __float2bfloat16(a_pf.z);
            __nv_bfloat16 h3 = __float2bfloat16(a_pf.w);
            __nv_bfloat16 l0 = __float2bfloat16(a_pf.x - __bfloat162float(h0));
            __nv_bfloat16 l1 = __float2bfloat16(a_pf.y - __bfloat162float(h1));
            __nv_bfloat16 l2 = __float2bfloat16(a_pf.z - __bfloat162float(h2));
            __nv_bfloat16 l3 = __float2bfloat16(a_pf.w - __bfloat162float(h3));
            uint2 hh = make_uint2(pack_bf16x2(h0, h1), pack_bf16x2(h2, h3));
            uint2 ll = make_uint2(pack_bf16x2(l0, l1), pack_bf16x2(l2, l3));
            *reinterpret_cast<uint2*>(&Ahi[a_r * A_STRIDE + a_c]) = hh;
            *reinterpret_cast<uint2*>(&Alo[a_r * A_STRIDE + a_c]) = ll;

            *reinterpret_cast<uint4*>(&Bhi[b_r * B_STRIDE + b_c])     = bh_pf[0];
            *reinterpret_cast<uint4*>(&Bhi[b_r * B_STRIDE + b_c + 8]) = bh_pf[1];
            *reinterpret_cast<uint4*>(&Blo[b_r * B_STRIDE + b_c])     = bl_pf[0];
            *reinterpret_cast<uint4*>(&Blo[b_r * B_STRIDE + b_c + 8]) = bl_pf[1];
        }
        __syncthreads();

        // ---- prefetch next chunk ----
        if (c < 15) {
            int k0 = (c + 1) * 32;
            a_pf = make_float4(0.f, 0.f, 0.f, 0.f);
            if (a_g < N_NODES)
                a_pf = *reinterpret_cast<const float4*>(feat + (long)a_g * IN_F + k0 + a_c);
            const uint4* ph = reinterpret_cast<const uint4*>(g_Whi + (k0 + b_r) * HD + b_c);
            const uint4* pl = reinterpret_cast<const uint4*>(g_Wlo + (k0 + b_r) * HD + b_c);
            bh_pf[0] = ph[0]; bh_pf[1] = ph[1];
            bl_pf[0] = pl[0]; bl_pf[1] = pl[1];
        }

        // ---- mma over the chunk: 2 k16 steps ----
#pragma unroll
        for (int ks = 0; ks < 32; ks += 16) {
            uint32_t ah[4], alr[4];
            {
                int r  = warp_m * 16 + (lane & 15);
                int cc = ks + (lane >> 4) * 8;
                uint32_t off = (uint32_t)(r * A_STRIDE + cc) * 2u;
                ldsm_x4(ah,  aHiB + off);
                ldsm_x4(alr, aLoB + off);
            }
            uint32_t bh[4][4], bl[4][4];
#pragma unroll
            for (int np = 0; np < 4; np++) {
                int kk = ks + (lane & 15);
                int nn = warp_n * 64 + np * 16 + (lane >> 4) * 8;
                uint32_t off = (uint32_t)(kk * B_STRIDE + nn) * 2u;
                ldsm_x4_t(bh[np], bHiB + off);
                ldsm_x4_t(bl[np], bLoB + off);
            }
#pragma unroll
            for (int nf = 0; nf < 8; nf++) {
                const uint32_t* bph = &bh[nf >> 1][(nf & 1) * 2];
                const uint32_t* bpl = &bl[nf >> 1][(nf & 1) * 2];
                mma16816(acc[nf], ah,  bph);
                mma16816(acc[nf], ah,  bpl);
                mma16816(acc[nf], alr, bph);
            }
        }
        __syncthreads();
    }

    // ---- epilogue: write g_ft + fused el/er (head == warp_n) ----
    const int head = warp_n;
    float alv[16], arv[16];
#pragma unroll
    for (int nf = 0; nf < 8; nf++) {
#pragma unroll
        for (int j = 0; j < 2; j++) {
            int col = nf * 8 + (lane & 3) * 2 + j;
            alv[nf * 2 + j] = al[head * 64 + col];
            arv[nf * 2 + j] = ar[head * 64 + col];
        }
    }

    int r0 = row_base + warp_m * 16 + (lane >> 2);
    int r1 = r0 + 8;
    float pl0 = 0.f, pr0 = 0.f, pl1 = 0.f, pr1 = 0.f;

#pragma unroll
    for (int nf = 0; nf < 8; nf++) {
        float c0 = acc[nf][0], c1 = acc[nf][1], c2 = acc[nf][2], c3 = acc[nf][3];
        int colg = head * 64 + nf * 8 + (lane & 3) * 2;
        if (r0 < N_NODES)
            *reinterpret_cast<float2*>(g_ft + (long)r0 * HD + colg) = make_float2(c0, c1);
        if (r1 < N_NODES)
            *reinterpret_cast<float2*>(g_ft + (long)r1 * HD + colg) = make_float2(c2, c3);
        pl0 = fmaf(c0, alv[nf * 2], fmaf(c1, alv[nf * 2 + 1], pl0));
        pr0 = fmaf(c0, arv[nf * 2], fmaf(c1, arv[nf * 2 + 1], pr0));
        pl1 = fmaf(c2, alv[nf * 2], fmaf(c3, alv[nf * 2 + 1], pl1));
        pr1 = fmaf(c2, arv[nf * 2], fmaf(c3, arv[nf * 2 + 1], pr1));
    }
#pragma unroll
    for (int off = 1; off < 4; off <<= 1) {
        pl0 += __shfl_xor_sync(0xffffffffu, pl0, off);
        pr0 += __shfl_xor_sync(0xffffffffu, pr0, off);
        pl1 += __shfl_xor_sync(0xffffffffu, pl1, off);
        pr1 += __shfl_xor_sync(0xffffffffu, pr1, off);
    }
    if ((lane & 3) == 0) {
        if (r0 < N_NODES) { g_el[r0 * NH + head] = pl0; g_er[r0 * NH + head] = pr0; }
        if (r1 < N_NODES) { g_el[r1 * NH + head] = pl1; g_er[r1 * NH + head] = pr1; }
    }
}

// ---------------- CSR build ---------------------------------------------------
__global__ void zero_kernel() {
    int i = blockIdx.x * blockDim.x + threadIdx.x;
    if (i < N_NODES) { g_deg[i] = 0; g_cursor[i] = 0; }
}

__global__ void hist_kernel(const int* __restrict__ dst) {
    int i = blockIdx.x * blockDim.x + threadIdx.x;
    if (i < N_EDGES) atomicAdd(&g_deg[dst[i]], 1);
}

__global__ void scan_kernel() {
    __shared__ int sums[1024];
    int tid = threadIdx.x;
    const int chunk = (N_NODES + 1023) / 1024;  // 49
    int lo = tid * chunk;
    int hi = lo + chunk; if (hi > N_NODES) hi = N_NODES;
    int s = 0;
    for (int i = lo; i < hi; i++) s += g_deg[i];
    sums[tid] = s;
    __syncthreads();
    for (int off = 1; off < 1024; off <<= 1) {
        int v = (tid >= off) ? sums[tid - off] : 0;
        __syncthreads();
        sums[tid] += v;
        __syncthreads();
    }
    int base = (tid == 0) ? 0 : sums[tid - 1];
    for (int i = lo; i < hi; i++) { g_row_start[i] = base; base += g_deg[i]; }
    if (tid == 1023) g_row_start[N_NODES] = sums[1023];
}

__global__ void scatter_kernel(const int* __restrict__ src, const int* __restrict__ dst) {
    int i = blockIdx.x * blockDim.x + threadIdx.x;
    if (i < N_EDGES) {
        int v = dst[i];
        int pos = g_row_start[v] + atomicAdd(&g_cursor[v], 1);
        g_csr_src[pos] = src[i];
    }
}

// ---------------- aggregation: one warp per destination node ------------------
__global__ __launch_bounds__(256)
void aggregate_kernel(float* __restrict__ out) {
    int v    = (blockIdx.x * blockDim.x + threadIdx.x) >> 5;
    int lane = threadIdx.x & 31;
    if (v >= N_NODES) return;
    int start = g_row_start[v];
    int end   = g_row_start[v + 1];

    // ---- pass 1: online softmax stats. 8 edge slots x 4 heads per warp.
    int hh   = lane & 3;
    int slot = lane >> 2;
    float er_h = g_er[v * NH + hh];
    float m = -1e30f, ssum = 0.f;
    for (int e = start + slot; e < end; e += 8) {
        int s = g_csr_src[e];
        float x = g_el[s * NH + hh] + er_h;
        x = (x > 0.f) ? x : 0.2f * x;
        float mn = fmaxf(m, x);
        ssum = ssum * __expf(m - mn) + __expf(x - mn);
        m = mn;
    }
#pragma unroll
    for (int off = 4; off < 32; off <<= 1) {
        float m2 = __shfl_xor_sync(0xffffffffu, m, off);
        float s2 = __shfl_xor_sync(0xffffffffu, ssum, off);
        float mn = fmaxf(m, m2);
        ssum = ssum * __expf(m - mn) + s2 * __expf(m2 - mn);
        m = mn;
    }

    // ---- pass 2: weighted gather. lane covers 8 features; head = lane>>3.
    int hg = lane >> 3;
    float m_g  = __shfl_sync(0xffffffffu, m, hg);
    float s_g  = __shfl_sync(0xffffffffu, ssum, hg);
    float er_g = __shfl_sync(0xffffffffu, er_h, hg);
    float inv = (s_g > 0.f) ? (1.0f / s_g) : 0.f;

    float acc[8];
#pragma unroll
    for (int k = 0; k < 8; k++) acc[k] = 0.f;

    for (int e = start; e < end; e++) {
        int s = g_csr_src[e];
        float x = g_el[s * NH + hg] + er_g;
        x = (x > 0.f) ? x : 0.2f * x;
        float wgt = __expf(x - m_g) * inv;
        const float4* p = reinterpret_cast<const float4*>(g_ft + (long)s * HD + lane * 8);
        float4 u0 = p[0], u1 = p[1];
        acc[0] = fmaf(wgt, u0.x, acc[0]);
        acc[1] = fmaf(wgt, u0.y, acc[1]);
        acc[2] = fmaf(wgt, u0.z, acc[2]);
        acc[3] = fmaf(wgt, u0.w, acc[3]);
        acc[4] = fmaf(wgt, u1.x, acc[4]);
        acc[5] = fmaf(wgt, u1.y, acc[5]);
        acc[6] = fmaf(wgt, u1.z, acc[6]);
        acc[7] = fmaf(wgt, u1.w, acc[7]);
    }
    float4* op = reinterpret_cast<float4*>(out + (long)v * HD + lane * 8);
    op[0] = make_float4(acc[0], acc[1], acc[2], acc[3]);
    op[1] = make_float4(acc[4], acc[5], acc[6], acc[7]);
}

// ---------------- launch ------------------------------------------------------
extern "C" void kernel_launch(void* const* d_in, const int* in_sizes, int n_in,
                              void* d_out, int out_size) {
    const float* feat = (const float*)d_in[0];
    const float* W    = (const float*)d_in[1];
    const float* al   = (const float*)d_in[2];
    const float* ar   = (const float*)d_in[3];
    const int*   src  = (const int*)d_in[4];
    const int*   dst  = (const int*)d_in[5];
    float* out = (float*)d_out;

    zero_kernel<<<(N_NODES + 255) / 256, 256>>>();
    wsplit_kernel<<<(IN_F * HD + 255) / 256, 256>>>(W);

    mma_gemm_kernel<<<(N_NODES + 63) / 64, 512>>>(feat, al, ar);

    hist_kernel<<<(N_EDGES + 255) / 256, 256>>>(dst);
    scan_kernel<<<1, 1024>>>();
    scatter_kernel<<<(N_EDGES + 255) / 256, 256>>>(src, dst);

    aggregate_kernel<<<(N_NODES * 32 + 255) / 256, 256>>>(out);
}

// round 5
// speedup vs baseline: 1.4674x; 1.0083x over previous
#include <cuda_runtime.h>
#include <cuda_bf16.h>
#include <cstdint>

#define N_NODES 50000
#define N_EDGES 800000
#define IN_F    512
#define HD      256
#define NH      4

// ---------------- scratch (static __device__ — no allocation) ----------------
__device__ float g_ft[N_NODES * HD];
__device__ float g_el[N_NODES * NH];
__device__ float g_er[N_NODES * NH];
__device__ int   g_deg[N_NODES];
__device__ int   g_cursor[N_NODES];
__device__ int   g_row_start[N_NODES + 1];
__device__ int   g_csr_src[N_EDGES];
__device__ __nv_bfloat16 g_Whi[IN_F * HD];   // [K=512][N=256] row-major, hi part
__device__ __nv_bfloat16 g_Wlo[IN_F * HD];   // lo part

// ---------------- helpers ------------------------------------------------------
__device__ __forceinline__ uint32_t smem_u32(const void* p) {
    uint32_t a;
    asm("{ .reg .u64 t; cvta.to.shared.u64 t, %1; cvt.u32.u64 %0, t; }"
        : "=r"(a) : "l"(p));
    return a;
}

__device__ __forceinline__ void ldsm_x4(uint32_t* r, uint32_t addr) {
    asm volatile("ldmatrix.sync.aligned.m8n8.x4.shared.b16 {%0,%1,%2,%3}, [%4];"
                 : "=r"(r[0]), "=r"(r[1]), "=r"(r[2]), "=r"(r[3]) : "r"(addr));
}
__device__ __forceinline__ void ldsm_x4_t(uint32_t* r, uint32_t addr) {
    asm volatile("ldmatrix.sync.aligned.m8n8.x4.trans.shared.b16 {%0,%1,%2,%3}, [%4];"
                 : "=r"(r[0]), "=r"(r[1]), "=r"(r[2]), "=r"(r[3]) : "r"(addr));
}
__device__ __forceinline__ void mma16816(float* d, const uint32_t* a, const uint32_t* b) {
    asm volatile("mma.sync.aligned.m16n8k16.row.col.f32.bf16.bf16.f32 "
                 "{%0,%1,%2,%3}, {%4,%5,%6,%7}, {%8,%9}, {%0,%1,%2,%3};"
                 : "+f"(d[0]), "+f"(d[1]), "+f"(d[2]), "+f"(d[3])
                 : "r"(a[0]), "r"(a[1]), "r"(a[2]), "r"(a[3]), "r"(b[0]), "r"(b[1]));
}

__device__ __forceinline__ uint32_t pack_bf16x2(__nv_bfloat16 a, __nv_bfloat16 b) {
    __nv_bfloat162 p = __halves2bfloat162(a, b);
    return *reinterpret_cast<uint32_t*>(&p);
}

// ---------------- W split (+ zero of deg/cursor fused) -------------------------
__global__ void wsplit_kernel(const float* __restrict__ W) {
    int i = blockIdx.x * blockDim.x + threadIdx.x;
    if (i < N_NODES) { g_deg[i] = 0; g_cursor[i] = 0; }
    if (i >= IN_F * HD) return;
    float w = W[i];
    __nv_bfloat16 hi = __float2bfloat16(w);
    float r = w - __bfloat162float(hi);
    g_Whi[i] = hi;
    g_Wlo[i] = __float2bfloat16(r);
}

// ---------------- mma.sync GEMM: g_ft = feat @ W, fused el/er ------------------
// CTA: 512 threads (16 warps, 4x4), tile 64(M) x 256(N). K in 16 chunks of 32.
// Double-buffered smem; warp tile 16(M) x 64(N) -> warp_n == head index.
#define A_STRIDE 40    // bf16 elems per A smem row (32 + 8 pad)
#define B_STRIDE 264   // bf16 elems per B smem row (256 + 8 pad)
#define A_BUF_B  (64 * A_STRIDE * 2)   // bytes per A buffer = 5120
#define B_BUF_B  (32 * B_STRIDE * 2)   // bytes per B buffer = 16896
// dynamic smem layout (byte offsets)
#define OFF_AHI(b) ((b) * A_BUF_B)                       // 0, 5120
#define OFF_ALO(b) (2 * A_BUF_B + (b) * A_BUF_B)         // 10240, 15360
#define OFF_BHI(b) (4 * A_BUF_B + (b) * B_BUF_B)         // 20480, 37376
#define OFF_BLO(b) (4 * A_BUF_B + 2 * B_BUF_B + (b) * B_BUF_B)  // 54272, 71168
#define GEMM_SMEM  (4 * A_BUF_B + 4 * B_BUF_B)           // 88064

__global__ __launch_bounds__(512, 1)
void mma_gemm_kernel(const float* __restrict__ feat,
                     const float* __restrict__ al,
                     const float* __restrict__ ar) {
    extern __shared__ char smem[];
    const uint32_t sb = smem_u32(smem);

    const int tid    = threadIdx.x;
    const int lane   = tid & 31;
    const int wid    = tid >> 5;
    const int warp_m = wid & 3;    // 0..3 -> 16 rows each
    const int warp_n = wid >> 2;   // 0..3 -> head / 64 cols each
    const int row_base = blockIdx.x * 64;

    // gmem load mapping
    const int a_r = tid >> 3;            // 0..63
    const int a_c = (tid & 7) * 4;       // 0..28
    const int a_g = row_base + a_r;
    const int b_r = tid >> 4;            // 0..31
    const int b_c = (tid & 15) * 16;     // 0..240

    // per-thread smem store addresses (byte offsets within a buffer)
    const uint32_t aStoreOff = (uint32_t)(a_r * A_STRIDE + a_c) * 2u;
    const uint32_t bStoreOff = (uint32_t)(b_r * B_STRIDE + b_c) * 2u;

    float acc[8][4];
#pragma unroll
    for (int nf = 0; nf < 8; nf++)
#pragma unroll
        for (int j = 0; j < 4; j++) acc[nf][j] = 0.f;

    float4 a_pf;
    uint4  bh_pf[2], bl_pf[2];

    // helper lambdas (inlined)
    auto load_chunk = [&](int c) {
        int k0 = c * 32;
        a_pf = make_float4(0.f, 0.f, 0.f, 0.f);
        if (a_g < N_NODES)
            a_pf = *reinterpret_cast<const float4*>(feat + (long)a_g * IN_F + k0 + a_c);
        const uint4* ph = reinterpret_cast<const uint4*>(g_Whi + (k0 + b_r) * HD + b_c);
        const uint4* pl = reinterpret_cast<const uint4*>(g_Wlo + (k0 + b_r) * HD + b_c);
        bh_pf[0] = ph[0]; bh_pf[1] = ph[1];
        bl_pf[0] = pl[0]; bl_pf[1] = pl[1];
    };
    auto store_chunk = [&](int buf) {
        __nv_bfloat16 h0 = __float2bfloat16(a_pf.x);
        __nv_bfloat16 h1 = __float2bfloat16(a_pf.y);
        __nv_bfloat16 h2 = __float2bfloat16(a_pf.z);
        __nv_bfloat16 h3 = __float2bfloat16(a_pf.w);
        __nv_bfloat16 l0 = __float2bfloat16(a_pf.x - __bfloat162float(h0));
        __nv_bfloat16 l1 = __float2bfloat16(a_pf.y - __bfloat162float(h1));
        __nv_bfloat16 l2 = __float2bfloat16(a_pf.z - __bfloat162float(h2));
        __nv_bfloat16 l3 = __float2bfloat16(a_pf.w - __bfloat162float(h3));
        uint2 hh = make_uint2(pack_bf16x2(h0, h1), pack_bf16x2(h2, h3));
        uint2 ll = make_uint2(pack_bf16x2(l0, l1), pack_bf16x2(l2, l3));
        *reinterpret_cast<uint2*>(smem + OFF_AHI(buf) + aStoreOff) = hh;
        *reinterpret_cast<uint2*>(smem + OFF_ALO(buf) + aStoreOff) = ll;
        *reinterpret_cast<uint4*>(smem + OFF_BHI(buf) + bStoreOff)      = bh_pf[0];
        *reinterpret_cast<uint4*>(smem + OFF_BHI(buf) + bStoreOff + 16) = bh_pf[1];
        *reinterpret_cast<uint4*>(smem + OFF_BLO(buf) + bStoreOff)      = bl_pf[0];
        *reinterpret_cast<uint4*>(smem + OFF_BLO(buf) + bStoreOff + 16) = bl_pf[1];
    };

    // per-warp ldsm base offsets
    const uint32_t aLdOffBase = (uint32_t)((warp_m * 16 + (lane & 15)) * A_STRIDE + (lane >> 4) * 8) * 2u;
    const uint32_t bLdRow     = (uint32_t)(lane & 15);
    const uint32_t bLdColBase = (uint32_t)(warp_n * 64 + (lane >> 4) * 8);

    // prologue
    load_chunk(0);
    store_chunk(0);
    load_chunk(1);

    for (int c = 0; c < 16; c++) {
        const int buf = c & 1;
        __syncthreads();
        if (c < 15) store_chunk(buf ^ 1);
        if (c < 14) load_chunk(c + 2);

        const uint32_t aHiB = sb + OFF_AHI(buf);
        const uint32_t aLoB = sb + OFF_ALO(buf);
        const uint32_t bHiB = sb + OFF_BHI(buf);
        const uint32_t bLoB = sb + OFF_BLO(buf);

#pragma unroll
        for (int ks = 0; ks < 32; ks += 16) {
            uint32_t ah[4], alr[4];
            {
                uint32_t off = aLdOffBase + (uint32_t)ks * 2u;
                ldsm_x4(ah,  aHiB + off);
                ldsm_x4(alr, aLoB + off);
            }
            uint32_t bh[4][4], bl[4][4];
#pragma unroll
            for (int np = 0; np < 4; np++) {
                uint32_t off = ((uint32_t)(ks + bLdRow) * B_STRIDE + bLdColBase + np * 16) * 2u;
                ldsm_x4_t(bh[np], bHiB + off);
                ldsm_x4_t(bl[np], bLoB + off);
            }
#pragma unroll
            for (int nf = 0; nf < 8; nf++) {
                const uint32_t* bph = &bh[nf >> 1][(nf & 1) * 2];
                const uint32_t* bpl = &bl[nf >> 1][(nf & 1) * 2];
                mma16816(acc[nf], ah,  bph);
                mma16816(acc[nf], ah,  bpl);
                mma16816(acc[nf], alr, bph);
            }
        }
    }

    // ---- epilogue: write g_ft + fused el/er (head == warp_n) ----
    const int head = warp_n;
    float alv[16], arv[16];
#pragma unroll
    for (int nf = 0; nf < 8; nf++) {
#pragma unroll
        for (int j = 0; j < 2; j++) {
            int col = nf * 8 + (lane & 3) * 2 + j;
            alv[nf * 2 + j] = al[head * 64 + col];
            arv[nf * 2 + j] = ar[head * 64 + col];
        }
    }

    int r0 = row_base + warp_m * 16 + (lane >> 2);
    int r1 = r0 + 8;
    float pl0 = 0.f, pr0 = 0.f, pl1 = 0.f, pr1 = 0.f;

#pragma unroll
    for (int nf = 0; nf < 8; nf++) {
        float c0 = acc[nf][0], c1 = acc[nf][1], c2 = acc[nf][2], c3 = acc[nf][3];
        int colg = head * 64 + nf * 8 + (lane & 3) * 2;
        if (r0 < N_NODES)
            *reinterpret_cast<float2*>(g_ft + (long)r0 * HD + colg) = make_float2(c0, c1);
        if (r1 < N_NODES)
            *reinterpret_cast<float2*>(g_ft + (long)r1 * HD + colg) = make_float2(c2, c3);
        pl0 = fmaf(c0, alv[nf * 2], fmaf(c1, alv[nf * 2 + 1], pl0));
        pr0 = fmaf(c0, arv[nf * 2], fmaf(c1, arv[nf * 2 + 1], pr0));
        pl1 = fmaf(c2, alv[nf * 2], fmaf(c3, alv[nf * 2 + 1], pl1));
        pr1 = fmaf(c2, arv[nf * 2], fmaf(c3, arv[nf * 2 + 1], pr1));
    }
#pragma unroll
    for (int off = 1; off < 4; off <<= 1) {
        pl0 += __shfl_xor_sync(0xffffffffu, pl0, off);
        pr0 += __shfl_xor_sync(0xffffffffu, pr0, off);
        pl1 += __shfl_xor_sync(0xffffffffu, pl1, off);
        pr1 += __shfl_xor_sync(0xffffffffu, pr1, off);
    }
    if ((lane & 3) == 0) {
        if (r0 < N_NODES) { g_el[r0 * NH + head] = pl0; g_er[r0 * NH + head] = pr0; }
        if (r1 < N_NODES) { g_el[r1 * NH + head] = pl1; g_er[r1 * NH + head] = pr1; }
    }
}

// ---------------- CSR build ---------------------------------------------------
__global__ void hist_kernel(const int* __restrict__ dst) {
    int i = blockIdx.x * blockDim.x + threadIdx.x;
    int base = i * 4;
    if (base + 3 < N_EDGES) {
        int4 d = *reinterpret_cast<const int4*>(dst + base);
        atomicAdd(&g_deg[d.x], 1);
        atomicAdd(&g_deg[d.y], 1);
        atomicAdd(&g_deg[d.z], 1);
        atomicAdd(&g_deg[d.w], 1);
    } else {
        for (int e = base; e < N_EDGES; e++) atomicAdd(&g_deg[dst[e]], 1);
    }
}

__global__ void scan_kernel() {
    __shared__ int sums[1024];
    int tid = threadIdx.x;
    const int chunk = (N_NODES + 1023) / 1024;  // 49
    int lo = tid * chunk;
    int hi = lo + chunk; if (hi > N_NODES) hi = N_NODES;
    int s = 0;
    for (int i = lo; i < hi; i++) s += g_deg[i];
    sums[tid] = s;
    __syncthreads();
    for (int off = 1; off < 1024; off <<= 1) {
        int v = (tid >= off) ? sums[tid - off] : 0;
        __syncthreads();
        sums[tid] += v;
        __syncthreads();
    }
    int base = (tid == 0) ? 0 : sums[tid - 1];
    for (int i = lo; i < hi; i++) { g_row_start[i] = base; base += g_deg[i]; }
    if (tid == 1023) g_row_start[N_NODES] = sums[1023];
}

__global__ void scatter_kernel(const int* __restrict__ src, const int* __restrict__ dst) {
    int i = blockIdx.x * blockDim.x + threadIdx.x;
    if (i < N_EDGES) {
        int v = dst[i];
        int pos = g_row_start[v] + atomicAdd(&g_cursor[v], 1);
        g_csr_src[pos] = src[i];
    }
}

// ---------------- aggregation: one warp per destination node ------------------
__global__ __launch_bounds__(256)
void aggregate_kernel(float* __restrict__ out) {
    int v    = (blockIdx.x * blockDim.x + threadIdx.x) >> 5;
    int lane = threadIdx.x & 31;
    if (v >= N_NODES) return;
    int start = g_row_start[v];
    int end   = g_row_start[v + 1];

    // ---- pass 1: online softmax stats. 8 edge slots x 4 heads per warp.
    int hh   = lane & 3;
    int slot = lane >> 2;
    float er_h = g_er[v * NH + hh];
    float m = -1e30f, ssum = 0.f;
    for (int e = start + slot; e < end; e += 8) {
        int s = g_csr_src[e];
        float x = g_el[s * NH + hh] + er_h;
        x = (x > 0.f) ? x : 0.2f * x;
        float mn = fmaxf(m, x);
        ssum = ssum * __expf(m - mn) + __expf(x - mn);
        m = mn;
    }
#pragma unroll
    for (int off = 4; off < 32; off <<= 1) {
        float m2 = __shfl_xor_sync(0xffffffffu, m, off);
        float s2 = __shfl_xor_sync(0xffffffffu, ssum, off);
        float mn = fmaxf(m, m2);
        ssum = ssum * __expf(m - mn) + s2 * __expf(m2 - mn);
        m = mn;
    }

    // ---- pass 2: weighted gather, unrolled x2 for MLP. head = lane>>3.
    int hg = lane >> 3;
    float m_g  = __shfl_sync(0xffffffffu, m, hg);
    float s_g  = __shfl_sync(0xffffffffu, ssum, hg);
    float er_g = __shfl_sync(0xffffffffu, er_h, hg);
    float inv = (s_g > 0.f) ? (1.0f / s_g) : 0.f;

    float acc[8];
#pragma unroll
    for (int k = 0; k < 8; k++) acc[k] = 0.f;

    int e = start;
    for (; e + 1 < end; e += 2) {
        int s0 = g_csr_src[e];
        int s1 = g_csr_src[e + 1];
        float x0 = g_el[s0 * NH + hg] + er_g;
        float x1 = g_el[s1 * NH + hg] + er_g;
        const float4* p0 = reinterpret_cast<const float4*>(g_ft + (long)s0 * HD + lane * 8);
        const float4* p1 = reinterpret_cast<const float4*>(g_ft + (long)s1 * HD + lane * 8);
        float4 a0 = p0[0], a1 = p0[1];
        float4 b0 = p1[0], b1 = p1[1];
        x0 = (x0 > 0.f) ? x0 : 0.2f * x0;
        x1 = (x1 > 0.f) ? x1 : 0.2f * x1;
        float w0 = __expf(x0 - m_g) * inv;
        float w1 = __expf(x1 - m_g) * inv;
        acc[0] = fmaf(w0, a0.x, acc[0]); acc[1] = fmaf(w0, a0.y, acc[1]);
        acc[2] = fmaf(w0, a0.z, acc[2]); acc[3] = fmaf(w0, a0.w, acc[3]);
        acc[4] = fmaf(w0, a1.x, acc[4]); acc[5] = fmaf(w0, a1.y, acc[5]);
        acc[6] = fmaf(w0, a1.z, acc[6]); acc[7] = fmaf(w0, a1.w, acc[7]);
        acc[0] = fmaf(w1, b0.x, acc[0]); acc[1] = fmaf(w1, b0.y, acc[1]);
        acc[2] = fmaf(w1, b0.z, acc[2]); acc[3] = fmaf(w1, b0.w, acc[3]);
        acc[4] = fmaf(w1, b1.x, acc[4]); acc[5] = fmaf(w1, b1.y, acc[5]);
        acc[6] = fmaf(w1, b1.z, acc[6]); acc[7] = fmaf(w1, b1.w, acc[7]);
    }
    if (e < end) {
        int s = g_csr_src[e];
        float x = g_el[s * NH + hg] + er_g;
        x = (x > 0.f) ? x : 0.2f * x;
        float wgt = __expf(x - m_g) * inv;
        const float4* p = reinterpret_cast<const float4*>(g_ft + (long)s * HD + lane * 8);
        float4 u0 = p[0], u1 = p[1];
        acc[0] = fmaf(wgt, u0.x, acc[0]); acc[1] = fmaf(wgt, u0.y, acc[1]);
        acc[2] = fmaf(wgt, u0.z, acc[2]); acc[3] = fmaf(wgt, u0.w, acc[3]);
        acc[4] = fmaf(wgt, u1.x, acc[4]); acc[5] = fmaf(wgt, u1.y, acc[5]);
        acc[6] = fmaf(wgt, u1.z, acc[6]); acc[7] = fmaf(wgt, u1.w, acc[7]);
    }
    float4* op = reinterpret_cast<float4*>(out + (long)v * HD + lane * 8);
    op[0] = make_float4(acc[0], acc[1], acc[2], acc[3]);
    op[1] = make_float4(acc[4], acc[5], acc[6], acc[7]);
}

// ---------------- launch ------------------------------------------------------
extern "C" void kernel_launch(void* const* d_in, const int* in_sizes, int n_in,
                              void* d_out, int out_size) {
    const float* feat = (const float*)d_in[0];
    const float* W    = (const float*)d_in[1];
    const float* al   = (const float*)d_in[2];
    const float* ar   = (const float*)d_in[3];
    const int*   src  = (const int*)d_in[4];
    const int*   dst  = (const int*)d_in[5];
    float* out = (float*)d_out;

    static int smem_set = 0;
    if (!smem_set) {
        cudaFuncSetAttribute(mma_gemm_kernel,
                             cudaFuncAttributeMaxDynamicSharedMemorySize, GEMM_SMEM);
        smem_set = 1;
    }

    wsplit_kernel<<<(IN_F * HD + 255) / 256, 256>>>(W);

    mma_gemm_kernel<<<(N_NODES + 63) / 64, 512, GEMM_SMEM>>>(feat, al, ar);

    hist_kernel<<<(N_EDGES / 4 + 255) / 256, 256>>>(dst);
    scan_kernel<<<1, 1024>>>();
    scatter_kernel<<<(N_EDGES + 255) / 256, 256>>>(src, dst);

    aggregate_kernel<<<(N_NODES * 32 + 255) / 256, 256>>>(out);
}

// round 6
// speedup vs baseline: 1.4679x; 1.0003x over previous
#include <cuda_runtime.h>
#include <cuda_bf16.h>
#include <cstdint>

#define N_NODES 50000
#define N_EDGES 800000
#define IN_F    512
#define HD      256
#define NH      4

// ---------------- scratch (static __device__ — no allocation) ----------------
__device__ float g_ft[N_NODES * HD];
__device__ float g_el[N_NODES * NH];
__device__ float g_er[N_NODES * NH];
__device__ int   g_deg[N_NODES];
__device__ int   g_cursor[N_NODES];
__device__ int   g_row_start[N_NODES + 1];
__device__ int   g_csr_src[N_EDGES];
__device__ __nv_bfloat16 g_Whi[IN_F * HD];   // [K=512][N=256] row-major, hi part
__device__ __nv_bfloat16 g_Wlo[IN_F * HD];   // lo part

// ---------------- helpers ------------------------------------------------------
__device__ __forceinline__ uint32_t smem_u32(const void* p) {
    uint32_t a;
    asm("{ .reg .u64 t; cvta.to.shared.u64 t, %1; cvt.u32.u64 %0, t; }"
        : "=r"(a) : "l"(p));
    return a;
}

__device__ __forceinline__ void ldsm_x4(uint32_t* r, uint32_t addr) {
    asm volatile("ldmatrix.sync.aligned.m8n8.x4.shared.b16 {%0,%1,%2,%3}, [%4];"
                 : "=r"(r[0]), "=r"(r[1]), "=r"(r[2]), "=r"(r[3]) : "r"(addr));
}
__device__ __forceinline__ void ldsm_x4_t(uint32_t* r, uint32_t addr) {
    asm volatile("ldmatrix.sync.aligned.m8n8.x4.trans.shared.b16 {%0,%1,%2,%3}, [%4];"
                 : "=r"(r[0]), "=r"(r[1]), "=r"(r[2]), "=r"(r[3]) : "r"(addr));
}
__device__ __forceinline__ void mma16816(float* d, const uint32_t* a, const uint32_t* b) {
    asm volatile("mma.sync.aligned.m16n8k16.row.col.f32.bf16.bf16.f32 "
                 "{%0,%1,%2,%3}, {%4,%5,%6,%7}, {%8,%9}, {%0,%1,%2,%3};"
                 : "+f"(d[0]), "+f"(d[1]), "+f"(d[2]), "+f"(d[3])
                 : "r"(a[0]), "r"(a[1]), "r"(a[2]), "r"(a[3]), "r"(b[0]), "r"(b[1]));
}

__device__ __forceinline__ uint32_t pack_bf16x2(__nv_bfloat16 a, __nv_bfloat16 b) {
    __nv_bfloat162 p = __halves2bfloat162(a, b);
    return *reinterpret_cast<uint32_t*>(&p);
}

// ---------------- W split (+ zero of deg/cursor fused) -------------------------
__global__ void wsplit_kernel(const float* __restrict__ W) {
    int i = blockIdx.x * blockDim.x + threadIdx.x;
    if (i < N_NODES) { g_deg[i] = 0; g_cursor[i] = 0; }
    if (i >= IN_F * HD) return;
    float w = W[i];
    __nv_bfloat16 hi = __float2bfloat16(w);
    float r = w - __bfloat162float(hi);
    g_Whi[i] = hi;
    g_Wlo[i] = __float2bfloat16(r);
}

// ---------------- mma.sync GEMM: g_ft = feat @ W, fused el/er ------------------
// CTA: 512 threads (16 warps, 4x4), tile 64(M) x 256(N). K in 16 chunks of 32.
// Double-buffered smem; warp tile 16(M) x 64(N) -> warp_n == head index.
#define A_STRIDE 40    // bf16 elems per A smem row (32 + 8 pad)
#define B_STRIDE 264   // bf16 elems per B smem row (256 + 8 pad)
#define A_BUF_B  (64 * A_STRIDE * 2)   // bytes per A buffer = 5120
#define B_BUF_B  (32 * B_STRIDE * 2)   // bytes per B buffer = 16896
// dynamic smem layout (byte offsets)
#define OFF_AHI(b) ((b) * A_BUF_B)                       // 0, 5120
#define OFF_ALO(b) (2 * A_BUF_B + (b) * A_BUF_B)         // 10240, 15360
#define OFF_BHI(b) (4 * A_BUF_B + (b) * B_BUF_B)         // 20480, 37376
#define OFF_BLO(b) (4 * A_BUF_B + 2 * B_BUF_B + (b) * B_BUF_B)  // 54272, 71168
#define GEMM_SMEM  (4 * A_BUF_B + 4 * B_BUF_B)           // 88064

__global__ __launch_bounds__(512, 1)
void mma_gemm_kernel(const float* __restrict__ feat,
                     const float* __restrict__ al,
                     const float* __restrict__ ar) {
    extern __shared__ char smem[];
    const uint32_t sb = smem_u32(smem);

    const int tid    = threadIdx.x;
    const int lane   = tid & 31;
    const int wid    = tid >> 5;
    const int warp_m = wid & 3;    // 0..3 -> 16 rows each
    const int warp_n = wid >> 2;   // 0..3 -> head / 64 cols each
    const int row_base = blockIdx.x * 64;

    // gmem load mapping
    const int a_r = tid >> 3;            // 0..63
    const int a_c = (tid & 7) * 4;       // 0..28
    const int a_g = row_base + a_r;
    const int b_r = tid >> 4;            // 0..31
    const int b_c = (tid & 15) * 16;     // 0..240

    // per-thread smem store addresses (byte offsets within a buffer)
    const uint32_t aStoreOff = (uint32_t)(a_r * A_STRIDE + a_c) * 2u;
    const uint32_t bStoreOff = (uint32_t)(b_r * B_STRIDE + b_c) * 2u;

    float acc[8][4];
#pragma unroll
    for (int nf = 0; nf < 8; nf++)
#pragma unroll
        for (int j = 0; j < 4; j++) acc[nf][j] = 0.f;

    float4 a_pf;
    uint4  bh_pf[2], bl_pf[2];

    // helper lambdas (inlined)
    auto load_chunk = [&](int c) {
        int k0 = c * 32;
        a_pf = make_float4(0.f, 0.f, 0.f, 0.f);
        if (a_g < N_NODES)
            a_pf = *reinterpret_cast<const float4*>(feat + (long)a_g * IN_F + k0 + a_c);
        const uint4* ph = reinterpret_cast<const uint4*>(g_Whi + (k0 + b_r) * HD + b_c);
        const uint4* pl = reinterpret_cast<const uint4*>(g_Wlo + (k0 + b_r) * HD + b_c);
        bh_pf[0] = ph[0]; bh_pf[1] = ph[1];
        bl_pf[0] = pl[0]; bl_pf[1] = pl[1];
    };
    auto store_chunk = [&](int buf) {
        __nv_bfloat16 h0 = __float2bfloat16(a_pf.x);
        __nv_bfloat16 h1 = __float2bfloat16(a_pf.y);
        __nv_bfloat16 h2 = __float2bfloat16(a_pf.z);
        __nv_bfloat16 h3 = __float2bfloat16(a_pf.w);
        __nv_bfloat16 l0 = __float2bfloat16(a_pf.x - __bfloat162float(h0));
        __nv_bfloat16 l1 = __float2bfloat16(a_pf.y - __bfloat162float(h1));
        __nv_bfloat16 l2 = __float2bfloat16(a_pf.z - __bfloat162float(h2));
        __nv_bfloat16 l3 = __float2bfloat16(a_pf.w - __bfloat162float(h3));
        uint2 hh = make_uint2(pack_bf16x2(h0, h1), pack_bf16x2(h2, h3));
        uint2 ll = make_uint2(pack_bf16x2(l0, l1), pack_bf16x2(l2, l3));
        *reinterpret_cast<uint2*>(smem + OFF_AHI(buf) + aStoreOff) = hh;
        *reinterpret_cast<uint2*>(smem + OFF_ALO(buf) + aStoreOff) = ll;
        *reinterpret_cast<uint4*>(smem + OFF_BHI(buf) + bStoreOff)      = bh_pf[0];
        *reinterpret_cast<uint4*>(smem + OFF_BHI(buf) + bStoreOff + 16) = bh_pf[1];
        *reinterpret_cast<uint4*>(smem + OFF_BLO(buf) + bStoreOff)      = bl_pf[0];
        *reinterpret_cast<uint4*>(smem + OFF_BLO(buf) + bStoreOff + 16) = bl_pf[1];
    };

    // per-warp ldsm base offsets
    const uint32_t aLdOffBase = (uint32_t)((warp_m * 16 + (lane & 15)) * A_STRIDE + (lane >> 4) * 8) * 2u;
    const uint32_t bLdRow     = (uint32_t)(lane & 15);
    const uint32_t bLdColBase = (uint32_t)(warp_n * 64 + (lane >> 4) * 8);

    // prologue
    load_chunk(0);
    store_chunk(0);
    load_chunk(1);

    for (int c = 0; c < 16; c++) {
        const int buf = c & 1;
        __syncthreads();
        if (c < 15) store_chunk(buf ^ 1);
        if (c < 14) load_chunk(c + 2);

        const uint32_t aHiB = sb + OFF_AHI(buf);
        const uint32_t aLoB = sb + OFF_ALO(buf);
        const uint32_t bHiB = sb + OFF_BHI(buf);
        const uint32_t bLoB = sb + OFF_BLO(buf);

#pragma unroll
        for (int ks = 0; ks < 32; ks += 16) {
            uint32_t ah[4], alr[4];
            {
                uint32_t off = aLdOffBase + (uint32_t)ks * 2u;
                ldsm_x4(ah,  aHiB + off);
                ldsm_x4(alr, aLoB + off);
            }
            uint32_t bh[4][4], bl[4][4];
#pragma unroll
            for (int np = 0; np < 4; np++) {
                uint32_t off = ((uint32_t)(ks + bLdRow) * B_STRIDE + bLdColBase + np * 16) * 2u;
                ldsm_x4_t(bh[np], bHiB + off);
                ldsm_x4_t(bl[np], bLoB + off);
            }
#pragma unroll
            for (int nf = 0; nf < 8; nf++) {
                const uint32_t* bph = &bh[nf >> 1][(nf & 1) * 2];
                const uint32_t* bpl = &bl[nf >> 1][(nf & 1) * 2];
                mma16816(acc[nf], ah,  bph);
                mma16816(acc[nf], ah,  bpl);
                mma16816(acc[nf], alr, bph);
            }
        }
    }

    // ---- epilogue: write g_ft + fused el/er (head == warp_n) ----
    const int head = warp_n;
    float alv[16], arv[16];
#pragma unroll
    for (int nf = 0; nf < 8; nf++) {
#pragma unroll
        for (int j = 0; j < 2; j++) {
            int col = nf * 8 + (lane & 3) * 2 + j;
            alv[nf * 2 + j] = al[head * 64 + col];
            arv[nf * 2 + j] = ar[head * 64 + col];
        }
    }

    int r0 = row_base + warp_m * 16 + (lane >> 2);
    int r1 = r0 + 8;
    float pl0 = 0.f, pr0 = 0.f, pl1 = 0.f, pr1 = 0.f;

#pragma unroll
    for (int nf = 0; nf < 8; nf++) {
        float c0 = acc[nf][0], c1 = acc[nf][1], c2 = acc[nf][2], c3 = acc[nf][3];
        int colg = head * 64 + nf * 8 + (lane & 3) * 2;
        if (r0 < N_NODES)
            *reinterpret_cast<float2*>(g_ft + (long)r0 * HD + colg) = make_float2(c0, c1);
        if (r1 < N_NODES)
            *reinterpret_cast<float2*>(g_ft + (long)r1 * HD + colg) = make_float2(c2, c3);
        pl0 = fmaf(c0, alv[nf * 2], fmaf(c1, alv[nf * 2 + 1], pl0));
        pr0 = fmaf(c0, arv[nf * 2], fmaf(c1, arv[nf * 2 + 1], pr0));
        pl1 = fmaf(c2, alv[nf * 2], fmaf(c3, alv[nf * 2 + 1], pl1));
        pr1 = fmaf(c2, arv[nf * 2], fmaf(c3, arv[nf * 2 + 1], pr1));
    }
#pragma unroll
    for (int off = 1; off < 4; off <<= 1) {
        pl0 += __shfl_xor_sync(0xffffffffu, pl0, off);
        pr0 += __shfl_xor_sync(0xffffffffu, pr0, off);
        pl1 += __shfl_xor_sync(0xffffffffu, pl1, off);
        pr1 += __shfl_xor_sync(0xffffffffu, pr1, off);
    }
    if ((lane & 3) == 0) {
        if (r0 < N_NODES) { g_el[r0 * NH + head] = pl0; g_er[r0 * NH + head] = pr0; }
        if (r1 < N_NODES) { g_el[r1 * NH + head] = pl1; g_er[r1 * NH + head] = pr1; }
    }
}

// ---------------- CSR build ---------------------------------------------------
__global__ void hist_kernel(const int* __restrict__ dst) {
    int i = blockIdx.x * blockDim.x + threadIdx.x;
    int base = i * 4;
    if (base + 3 < N_EDGES) {
        int4 d = *reinterpret_cast<const int4*>(dst + base);
        atomicAdd(&g_deg[d.x], 1);
        atomicAdd(&g_deg[d.y], 1);
        atomicAdd(&g_deg[d.z], 1);
        atomicAdd(&g_deg[d.w], 1);
    } else {
        for (int e = base; e < N_EDGES; e++) atomicAdd(&g_deg[dst[e]], 1);
    }
}

__global__ void scan_kernel() {
    __shared__ int sums[1024];
    int tid = threadIdx.x;
    const int chunk = (N_NODES + 1023) / 1024;  // 49
    int lo = tid * chunk;
    int hi = lo + chunk; if (hi > N_NODES) hi = N_NODES;
    int s = 0;
    for (int i = lo; i < hi; i++) s += g_deg[i];
    sums[tid] = s;
    __syncthreads();
    for (int off = 1; off < 1024; off <<= 1) {
        int v = (tid >= off) ? sums[tid - off] : 0;
        __syncthreads();
        sums[tid] += v;
        __syncthreads();
    }
    int base = (tid == 0) ? 0 : sums[tid - 1];
    for (int i = lo; i < hi; i++) { g_row_start[i] = base; base += g_deg[i]; }
    if (tid == 1023) g_row_start[N_NODES] = sums[1023];
}

__global__ void scatter_kernel(const int* __restrict__ src, const int* __restrict__ dst) {
    int i = blockIdx.x * blockDim.x + threadIdx.x;
    if (i < N_EDGES) {
        int v = dst[i];
        int pos = g_row_start[v] + atomicAdd(&g_cursor[v], 1);
        g_csr_src[pos] = src[i];
    }
}

// ---------------- aggregation: one warp per destination node ------------------
__global__ __launch_bounds__(256)
void aggregate_kernel(float* __restrict__ out) {
    int v    = (blockIdx.x * blockDim.x + threadIdx.x) >> 5;
    int lane = threadIdx.x & 31;
    if (v >= N_NODES) return;
    int start = g_row_start[v];
    int end   = g_row_start[v + 1];

    // ---- pass 1: online softmax stats. 8 edge slots x 4 heads per warp.
    int hh   = lane & 3;
    int slot = lane >> 2;
    float er_h = g_er[v * NH + hh];
    float m = -1e30f, ssum = 0.f;
    for (int e = start + slot; e < end; e += 8) {
        int s = g_csr_src[e];
        float x = g_el[s * NH + hh] + er_h;
        x = (x > 0.f) ? x : 0.2f * x;
        float mn = fmaxf(m, x);
        ssum = ssum * __expf(m - mn) + __expf(x - mn);
        m = mn;
    }
#pragma unroll
    for (int off = 4; off < 32; off <<= 1) {
        float m2 = __shfl_xor_sync(0xffffffffu, m, off);
        float s2 = __shfl_xor_sync(0xffffffffu, ssum, off);
        float mn = fmaxf(m, m2);
        ssum = ssum * __expf(m - mn) + s2 * __expf(m2 - mn);
        m = mn;
    }

    // ---- pass 2: weighted gather, unrolled x2 for MLP. head = lane>>3.
    int hg = lane >> 3;
    float m_g  = __shfl_sync(0xffffffffu, m, hg);
    float s_g  = __shfl_sync(0xffffffffu, ssum, hg);
    float er_g = __shfl_sync(0xffffffffu, er_h, hg);
    float inv = (s_g > 0.f) ? (1.0f / s_g) : 0.f;

    float acc[8];
#pragma unroll
    for (int k = 0; k < 8; k++) acc[k] = 0.f;

    int e = start;
    for (; e + 1 < end; e += 2) {
        int s0 = g_csr_src[e];
        int s1 = g_csr_src[e + 1];
        float x0 = g_el[s0 * NH + hg] + er_g;
        float x1 = g_el[s1 * NH + hg] + er_g;
        const float4* p0 = reinterpret_cast<const float4*>(g_ft + (long)s0 * HD + lane * 8);
        const float4* p1 = reinterpret_cast<const float4*>(g_ft + (long)s1 * HD + lane * 8);
        float4 a0 = p0[0], a1 = p0[1];
        float4 b0 = p1[0], b1 = p1[1];
        x0 = (x0 > 0.f) ? x0 : 0.2f * x0;
        x1 = (x1 > 0.f) ? x1 : 0.2f * x1;
        float w0 = __expf(x0 - m_g) * inv;
        float w1 = __expf(x1 - m_g) * inv;
        acc[0] = fmaf(w0, a0.x, acc[0]); acc[1] = fmaf(w0, a0.y, acc[1]);
        acc[2] = fmaf(w0, a0.z, acc[2]); acc[3] = fmaf(w0, a0.w, acc[3]);
        acc[4] = fmaf(w0, a1.x, acc[4]); acc[5] = fmaf(w0, a1.y, acc[5]);
        acc[6] = fmaf(w0, a1.z, acc[6]); acc[7] = fmaf(w0, a1.w, acc[7]);
        acc[0] = fmaf(w1, b0.x, acc[0]); acc[1] = fmaf(w1, b0.y, acc[1]);
        acc[2] = fmaf(w1, b0.z, acc[2]); acc[3] = fmaf(w1, b0.w, acc[3]);
        acc[4] = fmaf(w1, b1.x, acc[4]); acc[5] = fmaf(w1, b1.y, acc[5]);
        acc[6] = fmaf(w1, b1.z, acc[6]); acc[7] = fmaf(w1, b1.w, acc[7]);
    }
    if (e < end) {
        int s = g_csr_src[e];
        float x = g_el[s * NH + hg] + er_g;
        x = (x > 0.f) ? x : 0.2f * x;
        float wgt = __expf(x - m_g) * inv;
        const float4* p = reinterpret_cast<const float4*>(g_ft + (long)s * HD + lane * 8);
        float4 u0 = p[0], u1 = p[1];
        acc[0] = fmaf(wgt, u0.x, acc[0]); acc[1] = fmaf(wgt, u0.y, acc[1]);
        acc[2] = fmaf(wgt, u0.z, acc[2]); acc[3] = fmaf(wgt, u0.w, acc[3]);
        acc[4] = fmaf(wgt, u1.x, acc[4]); acc[5] = fmaf(wgt, u1.y, acc[5]);
        acc[6] = fmaf(wgt, u1.z, acc[6]); acc[7] = fmaf(wgt, u1.w, acc[7]);
    }
    float4* op = reinterpret_cast<float4*>(out + (long)v * HD + lane * 8);
    op[0] = make_float4(acc[0], acc[1], acc[2], acc[3]);
    op[1] = make_float4(acc[4], acc[5], acc[6], acc[7]);
}

// ---------------- launch ------------------------------------------------------
extern "C" void kernel_launch(void* const* d_in, const int* in_sizes, int n_in,
                              void* d_out, int out_size) {
    const float* feat = (const float*)d_in[0];
    const float* W    = (const float*)d_in[1];
    const float* al   = (const float*)d_in[2];
    const float* ar   = (const float*)d_in[3];
    const int*   src  = (const int*)d_in[4];
    const int*   dst  = (const int*)d_in[5];
    float* out = (float*)d_out;

    static int smem_set = 0;
    if (!smem_set) {
        cudaFuncSetAttribute(mma_gemm_kernel,
                             cudaFuncAttributeMaxDynamicSharedMemorySize, GEMM_SMEM);
        smem_set = 1;
    }

    wsplit_kernel<<<(IN_F * HD + 255) / 256, 256>>>(W);

    mma_gemm_kernel<<<(N_NODES + 63) / 64, 512, GEMM_SMEM>>>(feat, al, ar);

    hist_kernel<<<(N_EDGES / 4 + 255) / 256, 256>>>(dst);
    scan_kernel<<<1, 1024>>>();
    scatter_kernel<<<(N_EDGES + 255) / 256, 256>>>(src, dst);

    aggregate_kernel<<<(N_NODES * 32 + 255) / 256, 256>>>(out);
}

// round 7
// speedup vs baseline: 1.6810x; 1.1452x over previous
#include <cuda_runtime.h>
#include <cuda_bf16.h>
#include <cstdint>

#define N_NODES 50000
#define N_EDGES 800000
#define IN_F    512
#define HD      256
#define NH      4

// ---------------- scratch (static __device__ — no allocation) ----------------
__device__ float g_ft[N_NODES * HD];
__device__ float g_el[N_NODES * NH];
__device__ float g_er[N_NODES * NH];
__device__ int   g_deg[N_NODES];
__device__ int   g_cursor[N_NODES];
__device__ int   g_row_start[N_NODES + 1];
__device__ int   g_incl[N_NODES];
__device__ int   g_blksum[64];
__device__ int   g_blkoff[64];
__device__ int   g_csr_src[N_EDGES];
__device__ __nv_bfloat16 g_Whi[IN_F * HD];   // [K=512][N=256] row-major, hi part
__device__ __nv_bfloat16 g_Wlo[IN_F * HD];   // lo part

// ---------------- helpers ------------------------------------------------------
__device__ __forceinline__ uint32_t smem_u32(const void* p) {
    uint32_t a;
    asm("{ .reg .u64 t; cvta.to.shared.u64 t, %1; cvt.u32.u64 %0, t; }"
        : "=r"(a) : "l"(p));
    return a;
}

__device__ __forceinline__ void ldsm_x4(uint32_t* r, uint32_t addr) {
    asm volatile("ldmatrix.sync.aligned.m8n8.x4.shared.b16 {%0,%1,%2,%3}, [%4];"
                 : "=r"(r[0]), "=r"(r[1]), "=r"(r[2]), "=r"(r[3]) : "r"(addr));
}
__device__ __forceinline__ void ldsm_x4_t(uint32_t* r, uint32_t addr) {
    asm volatile("ldmatrix.sync.aligned.m8n8.x4.trans.shared.b16 {%0,%1,%2,%3}, [%4];"
                 : "=r"(r[0]), "=r"(r[1]), "=r"(r[2]), "=r"(r[3]) : "r"(addr));
}
__device__ __forceinline__ void mma16816(float* d, const uint32_t* a, const uint32_t* b) {
    asm volatile("mma.sync.aligned.m16n8k16.row.col.f32.bf16.bf16.f32 "
                 "{%0,%1,%2,%3}, {%4,%5,%6,%7}, {%8,%9}, {%0,%1,%2,%3};"
                 : "+f"(d[0]), "+f"(d[1]), "+f"(d[2]), "+f"(d[3])
                 : "r"(a[0]), "r"(a[1]), "r"(a[2]), "r"(a[3]), "r"(b[0]), "r"(b[1]));
}

__device__ __forceinline__ uint32_t pack_bf16x2(__nv_bfloat16 a, __nv_bfloat16 b) {
    __nv_bfloat162 p = __halves2bfloat162(a, b);
    return *reinterpret_cast<uint32_t*>(&p);
}

// ---------------- W split (+ zero of deg/cursor fused) -------------------------
__global__ void wsplit_kernel(const float* __restrict__ W) {
    int i = blockIdx.x * blockDim.x + threadIdx.x;
    if (i < N_NODES) { g_deg[i] = 0; g_cursor[i] = 0; }
    if (i >= IN_F * HD) return;
    float w = W[i];
    __nv_bfloat16 hi = __float2bfloat16(w);
    float r = w - __bfloat162float(hi);
    g_Whi[i] = hi;
    g_Wlo[i] = __float2bfloat16(r);
}

// ---------------- mma.sync GEMM: g_ft = feat @ W, fused el/er ------------------
// CTA: 512 threads (16 warps, 4x4), tile 64(M) x 256(N). K in 16 chunks of 32.
// Double-buffered smem; warp tile 16(M) x 64(N) -> warp_n == head index.
#define A_STRIDE 40    // bf16 elems per A smem row (32 + 8 pad)
#define B_STRIDE 264   // bf16 elems per B smem row (256 + 8 pad)
#define A_BUF_B  (64 * A_STRIDE * 2)   // bytes per A buffer = 5120
#define B_BUF_B  (32 * B_STRIDE * 2)   // bytes per B buffer = 16896
#define OFF_AHI(b) ((b) * A_BUF_B)
#define OFF_ALO(b) (2 * A_BUF_B + (b) * A_BUF_B)
#define OFF_BHI(b) (4 * A_BUF_B + (b) * B_BUF_B)
#define OFF_BLO(b) (4 * A_BUF_B + 2 * B_BUF_B + (b) * B_BUF_B)
#define GEMM_SMEM  (4 * A_BUF_B + 4 * B_BUF_B)           // 88064

__global__ __launch_bounds__(512, 1)
void mma_gemm_kernel(const float* __restrict__ feat,
                     const float* __restrict__ al,
                     const float* __restrict__ ar) {
    extern __shared__ char smem[];
    const uint32_t sb = smem_u32(smem);

    const int tid    = threadIdx.x;
    const int lane   = tid & 31;
    const int wid    = tid >> 5;
    const int warp_m = wid & 3;
    const int warp_n = wid >> 2;
    const int row_base = blockIdx.x * 64;

    const int a_r = tid >> 3;
    const int a_c = (tid & 7) * 4;
    const int a_g = row_base + a_r;
    const int b_r = tid >> 4;
    const int b_c = (tid & 15) * 16;

    const uint32_t aStoreOff = (uint32_t)(a_r * A_STRIDE + a_c) * 2u;
    const uint32_t bStoreOff = (uint32_t)(b_r * B_STRIDE + b_c) * 2u;

    float acc[8][4];
#pragma unroll
    for (int nf = 0; nf < 8; nf++)
#pragma unroll
        for (int j = 0; j < 4; j++) acc[nf][j] = 0.f;

    float4 a_pf;
    uint4  bh_pf[2], bl_pf[2];

    auto load_chunk = [&](int c) {
        int k0 = c * 32;
        a_pf = make_float4(0.f, 0.f, 0.f, 0.f);
        if (a_g < N_NODES)
            a_pf = *reinterpret_cast<const float4*>(feat + (long)a_g * IN_F + k0 + a_c);
        const uint4* ph = reinterpret_cast<const uint4*>(g_Whi + (k0 + b_r) * HD + b_c);
        const uint4* pl = reinterpret_cast<const uint4*>(g_Wlo + (k0 + b_r) * HD + b_c);
        bh_pf[0] = ph[0]; bh_pf[1] = ph[1];
        bl_pf[0] = pl[0]; bl_pf[1] = pl[1];
    };
    auto store_chunk = [&](int buf) {
        __nv_bfloat16 h0 = __float2bfloat16(a_pf.x);
        __nv_bfloat16 h1 = __float2bfloat16(a_pf.y);
        __nv_bfloat16 h2 = __float2bfloat16(a_pf.z);
        __nv_bfloat16 h3 = __float2bfloat16(a_pf.w);
        __nv_bfloat16 l0 = __float2bfloat16(a_pf.x - __bfloat162float(h0));
        __nv_bfloat16 l1 = __float2bfloat16(a_pf.y - __bfloat162float(h1));
        __nv_bfloat16 l2 = __float2bfloat16(a_pf.z - __bfloat162float(h2));
        __nv_bfloat16 l3 = __float2bfloat16(a_pf.w - __bfloat162float(h3));
        uint2 hh = make_uint2(pack_bf16x2(h0, h1), pack_bf16x2(h2, h3));
        uint2 ll = make_uint2(pack_bf16x2(l0, l1), pack_bf16x2(l2, l3));
        *reinterpret_cast<uint2*>(smem + OFF_AHI(buf) + aStoreOff) = hh;
        *reinterpret_cast<uint2*>(smem + OFF_ALO(buf) + aStoreOff) = ll;
        *reinterpret_cast<uint4*>(smem + OFF_BHI(buf) + bStoreOff)      = bh_pf[0];
        *reinterpret_cast<uint4*>(smem + OFF_BHI(buf) + bStoreOff + 16) = bh_pf[1];
        *reinterpret_cast<uint4*>(smem + OFF_BLO(buf) + bStoreOff)      = bl_pf[0];
        *reinterpret_cast<uint4*>(smem + OFF_BLO(buf) + bStoreOff + 16) = bl_pf[1];
    };

    const uint32_t aLdOffBase = (uint32_t)((warp_m * 16 + (lane & 15)) * A_STRIDE + (lane >> 4) * 8) * 2u;
    const uint32_t bLdRow     = (uint32_t)(lane & 15);
    const uint32_t bLdColBase = (uint32_t)(warp_n * 64 + (lane >> 4) * 8);

    load_chunk(0);
    store_chunk(0);
    load_chunk(1);

    for (int c = 0; c < 16; c++) {
        const int buf = c & 1;
        __syncthreads();
        if (c < 15) store_chunk(buf ^ 1);
        if (c < 14) load_chunk(c + 2);

        const uint32_t aHiB = sb + OFF_AHI(buf);
        const uint32_t aLoB = sb + OFF_ALO(buf);
        const uint32_t bHiB = sb + OFF_BHI(buf);
        const uint32_t bLoB = sb + OFF_BLO(buf);

#pragma unroll
        for (int ks = 0; ks < 32; ks += 16) {
            uint32_t ah[4], alr[4];
            {
                uint32_t off = aLdOffBase + (uint32_t)ks * 2u;
                ldsm_x4(ah,  aHiB + off);
                ldsm_x4(alr, aLoB + off);
            }
            uint32_t bh[4][4], bl[4][4];
#pragma unroll
            for (int np = 0; np < 4; np++) {
                uint32_t off = ((uint32_t)(ks + bLdRow) * B_STRIDE + bLdColBase + np * 16) * 2u;
                ldsm_x4_t(bh[np], bHiB + off);
                ldsm_x4_t(bl[np], bLoB + off);
            }
#pragma unroll
            for (int nf = 0; nf < 8; nf++) {
                const uint32_t* bph = &bh[nf >> 1][(nf & 1) * 2];
                const uint32_t* bpl = &bl[nf >> 1][(nf & 1) * 2];
                mma16816(acc[nf], ah,  bph);
                mma16816(acc[nf], ah,  bpl);
                mma16816(acc[nf], alr, bph);
            }
        }
    }

    // ---- epilogue: write g_ft + fused el/er (head == warp_n) ----
    const int head = warp_n;
    float alv[16], arv[16];
#pragma unroll
    for (int nf = 0; nf < 8; nf++) {
#pragma unroll
        for (int j = 0; j < 2; j++) {
            int col = nf * 8 + (lane & 3) * 2 + j;
            alv[nf * 2 + j] = al[head * 64 + col];
            arv[nf * 2 + j] = ar[head * 64 + col];
        }
    }

    int r0 = row_base + warp_m * 16 + (lane >> 2);
    int r1 = r0 + 8;
    float pl0 = 0.f, pr0 = 0.f, pl1 = 0.f, pr1 = 0.f;

#pragma unroll
    for (int nf = 0; nf < 8; nf++) {
        float c0 = acc[nf][0], c1 = acc[nf][1], c2 = acc[nf][2], c3 = acc[nf][3];
        int colg = head * 64 + nf * 8 + (lane & 3) * 2;
        if (r0 < N_NODES)
            *reinterpret_cast<float2*>(g_ft + (long)r0 * HD + colg) = make_float2(c0, c1);
        if (r1 < N_NODES)
            *reinterpret_cast<float2*>(g_ft + (long)r1 * HD + colg) = make_float2(c2, c3);
        pl0 = fmaf(c0, alv[nf * 2], fmaf(c1, alv[nf * 2 + 1], pl0));
        pr0 = fmaf(c0, arv[nf * 2], fmaf(c1, arv[nf * 2 + 1], pr0));
        pl1 = fmaf(c2, alv[nf * 2], fmaf(c3, alv[nf * 2 + 1], pl1));
        pr1 = fmaf(c2, arv[nf * 2], fmaf(c3, arv[nf * 2 + 1], pr1));
    }
#pragma unroll
    for (int off = 1; off < 4; off <<= 1) {
        pl0 += __shfl_xor_sync(0xffffffffu, pl0, off);
        pr0 += __shfl_xor_sync(0xffffffffu, pr0, off);
        pl1 += __shfl_xor_sync(0xffffffffu, pl1, off);
        pr1 += __shfl_xor_sync(0xffffffffu, pr1, off);
    }
    if ((lane & 3) == 0) {
        if (r0 < N_NODES) { g_el[r0 * NH + head] = pl0; g_er[r0 * NH + head] = pr0; }
        if (r1 < N_NODES) { g_el[r1 * NH + head] = pl1; g_er[r1 * NH + head] = pr1; }
    }
}

// ---------------- CSR build ---------------------------------------------------
__global__ void hist_kernel(const int* __restrict__ dst) {
    int i = blockIdx.x * blockDim.x + threadIdx.x;
    int base = i * 4;
    if (base + 3 < N_EDGES) {
        int4 d = *reinterpret_cast<const int4*>(dst + base);
        atomicAdd(&g_deg[d.x], 1);
        atomicAdd(&g_deg[d.y], 1);
        atomicAdd(&g_deg[d.z], 1);
        atomicAdd(&g_deg[d.w], 1);
    } else {
        for (int e = base; e < N_EDGES; e++) atomicAdd(&g_deg[dst[e]], 1);
    }
}

// 3-stage multi-block exclusive scan of g_deg -> g_row_start
#define SCAN_BLOCKS ((N_NODES + 1023) / 1024)   // 49

__global__ __launch_bounds__(1024)
void scan1_kernel() {
    int i = blockIdx.x * 1024 + threadIdx.x;
    int lane = threadIdx.x & 31, wid = threadIdx.x >> 5;
    int v = (i < N_NODES) ? g_deg[i] : 0;
    int x = v;
#pragma unroll
    for (int off = 1; off < 32; off <<= 1) {
        int y = __shfl_up_sync(0xffffffffu, x, off);
        if (lane >= off) x += y;
    }
    __shared__ int ws[32];
    if (lane == 31) ws[wid] = x;
    __syncthreads();
    if (wid == 0) {
        int y = ws[lane];
#pragma unroll
        for (int off = 1; off < 32; off <<= 1) {
            int z = __shfl_up_sync(0xffffffffu, y, off);
            if (lane >= off) y += z;
        }
        ws[lane] = y;
    }
    __syncthreads();
    if (wid > 0) x += ws[wid - 1];
    if (i < N_NODES) g_incl[i] = x;
    if (threadIdx.x == 1023) g_blksum[blockIdx.x] = x;
}

__global__ void scan2_kernel() {   // 1 block, 64 threads
    int t = threadIdx.x;
    int lane = t & 31, wid = t >> 5;
    int v = (t < SCAN_BLOCKS) ? g_blksum[t] : 0;
    int x = v;
#pragma unroll
    for (int off = 1; off < 32; off <<= 1) {
        int y = __shfl_up_sync(0xffffffffu, x, off);
        if (lane >= off) x += y;
    }
    __shared__ int ws[2];
    if (lane == 31) ws[wid] = x;
    __syncthreads();
    if (wid == 1) x += ws[0];
    g_blkoff[t] = x - v;            // exclusive block offset
    if (t == 63) g_row_start[N_NODES] = x;  // grand total
}

__global__ __launch_bounds__(1024)
void scan3_kernel() {
    int i = blockIdx.x * 1024 + threadIdx.x;
    if (i < N_NODES)
        g_row_start[i] = g_incl[i] - g_deg[i] + g_blkoff[i >> 10];
}

__global__ void scatter_kernel(const int* __restrict__ src, const int* __restrict__ dst) {
    int i = blockIdx.x * blockDim.x + threadIdx.x;
    int base = i * 4;
    if (base + 3 < N_EDGES) {
        int4 d = *reinterpret_cast<const int4*>(dst + base);
        int4 s = *reinterpret_cast<const int4*>(src + base);
        g_csr_src[g_row_start[d.x] + atomicAdd(&g_cursor[d.x], 1)] = s.x;
        g_csr_src[g_row_start[d.y] + atomicAdd(&g_cursor[d.y], 1)] = s.y;
        g_csr_src[g_row_start[d.z] + atomicAdd(&g_cursor[d.z], 1)] = s.z;
        g_csr_src[g_row_start[d.w] + atomicAdd(&g_cursor[d.w], 1)] = s.w;
    } else {
        for (int e = base; e < N_EDGES; e++) {
            int v = dst[e];
            g_csr_src[g_row_start[v] + atomicAdd(&g_cursor[v], 1)] = src[e];
        }
    }
}

// ---------------- aggregation: one warp per destination node ------------------
__global__ __launch_bounds__(256)
void aggregate_kernel(float* __restrict__ out) {
    int v    = (blockIdx.x * blockDim.x + threadIdx.x) >> 5;
    int lane = threadIdx.x & 31;
    if (v >= N_NODES) return;
    int start = g_row_start[v];
    int end   = g_row_start[v + 1];

    // ---- pass 1: online softmax stats. 8 edge slots x 4 heads per warp.
    int hh   = lane & 3;
    int slot = lane >> 2;
    float er_h = g_er[v * NH + hh];
    float m = -1e30f, ssum = 0.f;
    for (int e = start + slot; e < end; e += 8) {
        int s = g_csr_src[e];
        float x = g_el[s * NH + hh] + er_h;
        x = (x > 0.f) ? x : 0.2f * x;
        float mn = fmaxf(m, x);
        ssum = ssum * __expf(m - mn) + __expf(x - mn);
        m = mn;
    }
#pragma unroll
    for (int off = 4; off < 32; off <<= 1) {
        float m2 = __shfl_xor_sync(0xffffffffu, m, off);
        float s2 = __shfl_xor_sync(0xffffffffu, ssum, off);
        float mn = fmaxf(m, m2);
        ssum = ssum * __expf(m - mn) + s2 * __expf(m2 - mn);
        m = mn;
    }

    // ---- pass 2: weighted gather, unrolled x2 for MLP. head = lane>>3.
    int hg = lane >> 3;
    float m_g  = __shfl_sync(0xffffffffu, m, hg);
    float s_g  = __shfl_sync(0xffffffffu, ssum, hg);
    float er_g = __shfl_sync(0xffffffffu, er_h, hg);
    float inv = (s_g > 0.f) ? (1.0f / s_g) : 0.f;

    float acc[8];
#pragma unroll
    for (int k = 0; k < 8; k++) acc[k] = 0.f;

    int e = start;
    for (; e + 1 < end; e += 2) {
        int s0 = g_csr_src[e];
        int s1 = g_csr_src[e + 1];
        float x0 = g_el[s0 * NH + hg] + er_g;
        float x1 = g_el[s1 * NH + hg] + er_g;
        const float4* p0 = reinterpret_cast<const float4*>(g_ft + (long)s0 * HD + lane * 8);
        const float4* p1 = reinterpret_cast<const float4*>(g_ft + (long)s1 * HD + lane * 8);
        float4 a0 = p0[0], a1 = p0[1];
        float4 b0 = p1[0], b1 = p1[1];
        x0 = (x0 > 0.f) ? x0 : 0.2f * x0;
        x1 = (x1 > 0.f) ? x1 : 0.2f * x1;
        float w0 = __expf(x0 - m_g) * inv;
        float w1 = __expf(x1 - m_g) * inv;
        acc[0] = fmaf(w0, a0.x, acc[0]); acc[1] = fmaf(w0, a0.y, acc[1]);
        acc[2] = fmaf(w0, a0.z, acc[2]); acc[3] = fmaf(w0, a0.w, acc[3]);
        acc[4] = fmaf(w0, a1.x, acc[4]); acc[5] = fmaf(w0, a1.y, acc[5]);
        acc[6] = fmaf(w0, a1.z, acc[6]); acc[7] = fmaf(w0, a1.w, acc[7]);
        acc[0] = fmaf(w1, b0.x, acc[0]); acc[1] = fmaf(w1, b0.y, acc[1]);
        acc[2] = fmaf(w1, b0.z, acc[2]); acc[3] = fmaf(w1, b0.w, acc[3]);
        acc[4] = fmaf(w1, b1.x, acc[4]); acc[5] = fmaf(w1, b1.y, acc[5]);
        acc[6] = fmaf(w1, b1.z, acc[6]); acc[7] = fmaf(w1, b1.w, acc[7]);
    }
    if (e < end) {
        int s = g_csr_src[e];
        float x = g_el[s * NH + hg] + er_g;
        x = (x > 0.f) ? x : 0.2f * x;
        float wgt = __expf(x - m_g) * inv;
        const float4* p = reinterpret_cast<const float4*>(g_ft + (long)s * HD + lane * 8);
        float4 u0 = p[0], u1 = p[1];
        acc[0] = fmaf(wgt, u0.x, acc[0]); acc[1] = fmaf(wgt, u0.y, acc[1]);
        acc[2] = fmaf(wgt, u0.z, acc[2]); acc[3] = fmaf(wgt, u0.w, acc[3]);
        acc[4] = fmaf(wgt, u1.x, acc[4]); acc[5] = fmaf(wgt, u1.y, acc[5]);
        acc[6] = fmaf(wgt, u1.z, acc[6]); acc[7] = fmaf(wgt, u1.w, acc[7]);
    }
    float4* op = reinterpret_cast<float4*>(out + (long)v * HD + lane * 8);
    op[0] = make_float4(acc[0], acc[1], acc[2], acc[3]);
    op[1] = make_float4(acc[4], acc[5], acc[6], acc[7]);
}

// ---------------- launch ------------------------------------------------------
extern "C" void kernel_launch(void* const* d_in, const int* in_sizes, int n_in,
                              void* d_out, int out_size) {
    const float* feat = (const float*)d_in[0];
    const float* W    = (const float*)d_in[1];
    const float* al   = (const float*)d_in[2];
    const float* ar   = (const float*)d_in[3];
    const int*   src  = (const int*)d_in[4];
    const int*   dst  = (const int*)d_in[5];
    float* out = (float*)d_out;

    static int smem_set = 0;
    if (!smem_set) {
        cudaFuncSetAttribute(mma_gemm_kernel,
                             cudaFuncAttributeMaxDynamicSharedMemorySize, GEMM_SMEM);
        smem_set = 1;
    }

    wsplit_kernel<<<(IN_F * HD + 255) / 256, 256>>>(W);

    mma_gemm_kernel<<<(N_NODES + 63) / 64, 512, GEMM_SMEM>>>(feat, al, ar);

    hist_kernel<<<(N_EDGES / 4 + 255) / 256, 256>>>(dst);
    scan1_kernel<<<SCAN_BLOCKS, 1024>>>();
    scan2_kernel<<<1, 64>>>();
    scan3_kernel<<<SCAN_BLOCKS, 1024>>>();
    scatter_kernel<<<(N_EDGES / 4 + 255) / 256, 256>>>(src, dst);

    aggregate_kernel<<<(N_NODES * 32 + 255) / 256, 256>>>(out);
}

// round 8
// speedup vs baseline: 1.8001x; 1.0709x over previous
#include <cuda_runtime.h>
#include <cuda_bf16.h>
#include <cstdint>

#define N_NODES 50000
#define N_EDGES 800000
#define IN_F    512
#define HD      256
#define NH      4

// ---------------- scratch (static __device__ — no allocation) ----------------
__device__ float g_ft[N_NODES * HD];
__device__ float g_el[N_NODES * NH];
__device__ float g_er[N_NODES * NH];
__device__ int   g_deg[N_NODES];
__device__ int   g_cursor[N_NODES];
__device__ int   g_row_start[N_NODES + 1];
__device__ int   g_incl[N_NODES];
__device__ int   g_blksum[64];
__device__ int   g_blkoff[64];
__device__ int   g_node_ctr;
__device__ int   g_csr_src[N_EDGES];
__device__ __nv_bfloat16 g_Whi[IN_F * HD];   // [K=512][N=256] row-major, hi part
__device__ __nv_bfloat16 g_Wlo[IN_F * HD];   // lo part

// ---------------- helpers ------------------------------------------------------
__device__ __forceinline__ uint32_t smem_u32(const void* p) {
    uint32_t a;
    asm("{ .reg .u64 t; cvta.to.shared.u64 t, %1; cvt.u32.u64 %0, t; }"
        : "=r"(a) : "l"(p));
    return a;
}

__device__ __forceinline__ void ldsm_x4(uint32_t* r, uint32_t addr) {
    asm volatile("ldmatrix.sync.aligned.m8n8.x4.shared.b16 {%0,%1,%2,%3}, [%4];"
                 : "=r"(r[0]), "=r"(r[1]), "=r"(r[2]), "=r"(r[3]) : "r"(addr));
}
__device__ __forceinline__ void ldsm_x4_t(uint32_t* r, uint32_t addr) {
    asm volatile("ldmatrix.sync.aligned.m8n8.x4.trans.shared.b16 {%0,%1,%2,%3}, [%4];"
                 : "=r"(r[0]), "=r"(r[1]), "=r"(r[2]), "=r"(r[3]) : "r"(addr));
}
__device__ __forceinline__ void mma16816(float* d, const uint32_t* a, const uint32_t* b) {
    asm volatile("mma.sync.aligned.m16n8k16.row.col.f32.bf16.bf16.f32 "
                 "{%0,%1,%2,%3}, {%4,%5,%6,%7}, {%8,%9}, {%0,%1,%2,%3};"
                 : "+f"(d[0]), "+f"(d[1]), "+f"(d[2]), "+f"(d[3])
                 : "r"(a[0]), "r"(a[1]), "r"(a[2]), "r"(a[3]), "r"(b[0]), "r"(b[1]));
}

__device__ __forceinline__ uint32_t pack_bf16x2(__nv_bfloat16 a, __nv_bfloat16 b) {
    __nv_bfloat162 p = __halves2bfloat162(a, b);
    return *reinterpret_cast<uint32_t*>(&p);
}

// ---------------- W split ------------------------------------------------------
__global__ void wsplit_kernel(const float* __restrict__ W) {
    int i = blockIdx.x * blockDim.x + threadIdx.x;
    if (i >= IN_F * HD) return;
    float w = W[i];
    __nv_bfloat16 hi = __float2bfloat16(w);
    float r = w - __bfloat162float(hi);
    g_Whi[i] = hi;
    g_Wlo[i] = __float2bfloat16(r);
}

// zero of deg/cursor lives on the CSR stream
__global__ void zero_kernel() {
    int i = blockIdx.x * blockDim.x + threadIdx.x;
    if (i < N_NODES) { g_deg[i] = 0; g_cursor[i] = 0; }
}

// ---------------- mma.sync GEMM: g_ft = feat @ W, fused el/er ------------------
// CTA: 512 threads (16 warps, 4x4), tile 64(M) x 256(N). K in 16 chunks of 32.
// Double-buffered smem; warp tile 16(M) x 64(N) -> warp_n == head index.
#define A_STRIDE 40    // bf16 elems per A smem row (32 + 8 pad)
#define B_STRIDE 264   // bf16 elems per B smem row (256 + 8 pad)
#define A_BUF_B  (64 * A_STRIDE * 2)   // bytes per A buffer = 5120
#define B_BUF_B  (32 * B_STRIDE * 2)   // bytes per B buffer = 16896
#define OFF_AHI(b) ((b) * A_BUF_B)
#define OFF_ALO(b) (2 * A_BUF_B + (b) * A_BUF_B)
#define OFF_BHI(b) (4 * A_BUF_B + (b) * B_BUF_B)
#define OFF_BLO(b) (4 * A_BUF_B + 2 * B_BUF_B + (b) * B_BUF_B)
#define GEMM_SMEM  (4 * A_BUF_B + 4 * B_BUF_B)           // 88064

__global__ __launch_bounds__(512, 1)
void mma_gemm_kernel(const float* __restrict__ feat,
                     const float* __restrict__ al,
                     const float* __restrict__ ar) {
    extern __shared__ char smem[];
    const uint32_t sb = smem_u32(smem);

    const int tid    = threadIdx.x;
    const int lane   = tid & 31;
    const int wid    = tid >> 5;
    const int warp_m = wid & 3;
    const int warp_n = wid >> 2;
    const int row_base = blockIdx.x * 64;

    const int a_r = tid >> 3;
    const int a_c = (tid & 7) * 4;
    const int a_g = row_base + a_r;
    const int b_r = tid >> 4;
    const int b_c = (tid & 15) * 16;

    const uint32_t aStoreOff = (uint32_t)(a_r * A_STRIDE + a_c) * 2u;
    const uint32_t bStoreOff = (uint32_t)(b_r * B_STRIDE + b_c) * 2u;

    float acc[8][4];
#pragma unroll
    for (int nf = 0; nf < 8; nf++)
#pragma unroll
        for (int j = 0; j < 4; j++) acc[nf][j] = 0.f;

    float4 a_pf;
    uint4  bh_pf[2], bl_pf[2];

    auto load_chunk = [&](int c) {
        int k0 = c * 32;
        a_pf = make_float4(0.f, 0.f, 0.f, 0.f);
        if (a_g < N_NODES)
            a_pf = *reinterpret_cast<const float4*>(feat + (long)a_g * IN_F + k0 + a_c);
        const uint4* ph = reinterpret_cast<const uint4*>(g_Whi + (k0 + b_r) * HD + b_c);
        const uint4* pl = reinterpret_cast<const uint4*>(g_Wlo + (k0 + b_r) * HD + b_c);
        bh_pf[0] = ph[0]; bh_pf[1] = ph[1];
        bl_pf[0] = pl[0]; bl_pf[1] = pl[1];
    };
    auto store_chunk = [&](int buf) {
        __nv_bfloat16 h0 = __float2bfloat16(a_pf.x);
        __nv_bfloat16 h1 = __float2bfloat16(a_pf.y);
        __nv_bfloat16 h2 = __float2bfloat16(a_pf.z);
        __nv_bfloat16 h3 = __float2bfloat16(a_pf.w);
        __nv_bfloat16 l0 = __float2bfloat16(a_pf.x - __bfloat162float(h0));
        __nv_bfloat16 l1 = __float2bfloat16(a_pf.y - __bfloat162float(h1));
        __nv_bfloat16 l2 = __float2bfloat16(a_pf.z - __bfloat162float(h2));
        __nv_bfloat16 l3 = __float2bfloat16(a_pf.w - __bfloat162float(h3));
        uint2 hh = make_uint2(pack_bf16x2(h0, h1), pack_bf16x2(h2, h3));
        uint2 ll = make_uint2(pack_bf16x2(l0, l1), pack_bf16x2(l2, l3));
        *reinterpret_cast<uint2*>(smem + OFF_AHI(buf) + aStoreOff) = hh;
        *reinterpret_cast<uint2*>(smem + OFF_ALO(buf) + aStoreOff) = ll;
        *reinterpret_cast<uint4*>(smem + OFF_BHI(buf) + bStoreOff)      = bh_pf[0];
        *reinterpret_cast<uint4*>(smem + OFF_BHI(buf) + bStoreOff + 16) = bh_pf[1];
        *reinterpret_cast<uint4*>(smem + OFF_BLO(buf) + bStoreOff)      = bl_pf[0];
        *reinterpret_cast<uint4*>(smem + OFF_BLO(buf) + bStoreOff + 16) = bl_pf[1];
    };

    const uint32_t aLdOffBase = (uint32_t)((warp_m * 16 + (lane & 15)) * A_STRIDE + (lane >> 4) * 8) * 2u;
    const uint32_t bLdRow     = (uint32_t)(lane & 15);
    const uint32_t bLdColBase = (uint32_t)(warp_n * 64 + (lane >> 4) * 8);

    load_chunk(0);
    store_chunk(0);
    load_chunk(1);

    for (int c = 0; c < 16; c++) {
        const int buf = c & 1;
        __syncthreads();
        if (c < 15) store_chunk(buf ^ 1);
        if (c < 14) load_chunk(c + 2);

        const uint32_t aHiB = sb + OFF_AHI(buf);
        const uint32_t aLoB = sb + OFF_ALO(buf);
        const uint32_t bHiB = sb + OFF_BHI(buf);
        const uint32_t bLoB = sb + OFF_BLO(buf);

#pragma unroll
        for (int ks = 0; ks < 32; ks += 16) {
            uint32_t ah[4], alr[4];
            {
                uint32_t off = aLdOffBase + (uint32_t)ks * 2u;
                ldsm_x4(ah,  aHiB + off);
                ldsm_x4(alr, aLoB + off);
            }
            uint32_t bh[4][4], bl[4][4];
#pragma unroll
            for (int np = 0; np < 4; np++) {
                uint32_t off = ((uint32_t)(ks + bLdRow) * B_STRIDE + bLdColBase + np * 16) * 2u;
                ldsm_x4_t(bh[np], bHiB + off);
                ldsm_x4_t(bl[np], bLoB + off);
            }
#pragma unroll
            for (int nf = 0; nf < 8; nf++) {
                const uint32_t* bph = &bh[nf >> 1][(nf & 1) * 2];
                const uint32_t* bpl = &bl[nf >> 1][(nf & 1) * 2];
                mma16816(acc[nf], ah,  bph);
                mma16816(acc[nf], ah,  bpl);
                mma16816(acc[nf], alr, bph);
            }
        }
    }

    // ---- epilogue: write g_ft + fused el/er (head == warp_n) ----
    const int head = warp_n;
    float alv[16], arv[16];
#pragma unroll
    for (int nf = 0; nf < 8; nf++) {
#pragma unroll
        for (int j = 0; j < 2; j++) {
            int col = nf * 8 + (lane & 3) * 2 + j;
            alv[nf * 2 + j] = al[head * 64 + col];
            arv[nf * 2 + j] = ar[head * 64 + col];
        }
    }

    int r0 = row_base + warp_m * 16 + (lane >> 2);
    int r1 = r0 + 8;
    float pl0 = 0.f, pr0 = 0.f, pl1 = 0.f, pr1 = 0.f;

#pragma unroll
    for (int nf = 0; nf < 8; nf++) {
        float c0 = acc[nf][0], c1 = acc[nf][1], c2 = acc[nf][2], c3 = acc[nf][3];
        int colg = head * 64 + nf * 8 + (lane & 3) * 2;
        if (r0 < N_NODES)
            *reinterpret_cast<float2*>(g_ft + (long)r0 * HD + colg) = make_float2(c0, c1);
        if (r1 < N_NODES)
            *reinterpret_cast<float2*>(g_ft + (long)r1 * HD + colg) = make_float2(c2, c3);
        pl0 = fmaf(c0, alv[nf * 2], fmaf(c1, alv[nf * 2 + 1], pl0));
        pr0 = fmaf(c0, arv[nf * 2], fmaf(c1, arv[nf * 2 + 1], pr0));
        pl1 = fmaf(c2, alv[nf * 2], fmaf(c3, alv[nf * 2 + 1], pl1));
        pr1 = fmaf(c2, arv[nf * 2], fmaf(c3, arv[nf * 2 + 1], pr1));
    }
#pragma unroll
    for (int off = 1; off < 4; off <<= 1) {
        pl0 += __shfl_xor_sync(0xffffffffu, pl0, off);
        pr0 += __shfl_xor_sync(0xffffffffu, pr0, off);
        pl1 += __shfl_xor_sync(0xffffffffu, pl1, off);
        pr1 += __shfl_xor_sync(0xffffffffu, pr1, off);
    }
    if ((lane & 3) == 0) {
        if (r0 < N_NODES) { g_el[r0 * NH + head] = pl0; g_er[r0 * NH + head] = pr0; }
        if (r1 < N_NODES) { g_el[r1 * NH + head] = pl1; g_er[r1 * NH + head] = pr1; }
    }
}

// ---------------- CSR build ---------------------------------------------------
__global__ void hist_kernel(const int* __restrict__ dst) {
    int i = blockIdx.x * blockDim.x + threadIdx.x;
    int base = i * 4;
    if (base + 3 < N_EDGES) {
        int4 d = *reinterpret_cast<const int4*>(dst + base);
        atomicAdd(&g_deg[d.x], 1);
        atomicAdd(&g_deg[d.y], 1);
        atomicAdd(&g_deg[d.z], 1);
        atomicAdd(&g_deg[d.w], 1);
    } else {
        for (int e = base; e < N_EDGES; e++) atomicAdd(&g_deg[dst[e]], 1);
    }
}

// 3-stage multi-block exclusive scan of g_deg -> g_row_start
#define SCAN_BLOCKS ((N_NODES + 1023) / 1024)   // 49

__global__ __launch_bounds__(1024)
void scan1_kernel() {
    int i = blockIdx.x * 1024 + threadIdx.x;
    int lane = threadIdx.x & 31, wid = threadIdx.x >> 5;
    int v = (i < N_NODES) ? g_deg[i] : 0;
    int x = v;
#pragma unroll
    for (int off = 1; off < 32; off <<= 1) {
        int y = __shfl_up_sync(0xffffffffu, x, off);
        if (lane >= off) x += y;
    }
    __shared__ int ws[32];
    if (lane == 31) ws[wid] = x;
    __syncthreads();
    if (wid == 0) {
        int y = ws[lane];
#pragma unroll
        for (int off = 1; off < 32; off <<= 1) {
            int z = __shfl_up_sync(0xffffffffu, y, off);
            if (lane >= off) y += z;
        }
        ws[lane] = y;
    }
    __syncthreads();
    if (wid > 0) x += ws[wid - 1];
    if (i < N_NODES) g_incl[i] = x;
    if (threadIdx.x == 1023) g_blksum[blockIdx.x] = x;
}

__global__ void scan2_kernel() {   // 1 block, 64 threads
    int t = threadIdx.x;
    int lane = t & 31, wid = t >> 5;
    int v = (t < SCAN_BLOCKS) ? g_blksum[t] : 0;
    int x = v;
#pragma unroll
    for (int off = 1; off < 32; off <<= 1) {
        int y = __shfl_up_sync(0xffffffffu, x, off);
        if (lane >= off) x += y;
    }
    __shared__ int ws[2];
    if (lane == 31) ws[wid] = x;
    __syncthreads();
    if (wid == 1) x += ws[0];
    g_blkoff[t] = x - v;            // exclusive block offset
    if (t == 63) g_row_start[N_NODES] = x;  // grand total
    if (t == 0) g_node_ctr = 0;     // reset aggregate ticket counter (every replay)
}

__global__ __launch_bounds__(1024)
void scan3_kernel() {
    int i = blockIdx.x * 1024 + threadIdx.x;
    if (i < N_NODES)
        g_row_start[i] = g_incl[i] - g_deg[i] + g_blkoff[i >> 10];
}

__global__ void scatter_kernel(const int* __restrict__ src, const int* __restrict__ dst) {
    int i = blockIdx.x * blockDim.x + threadIdx.x;
    int base = i * 4;
    if (base + 3 < N_EDGES) {
        int4 d = *reinterpret_cast<const int4*>(dst + base);
        int4 s = *reinterpret_cast<const int4*>(src + base);
        g_csr_src[g_row_start[d.x] + atomicAdd(&g_cursor[d.x], 1)] = s.x;
        g_csr_src[g_row_start[d.y] + atomicAdd(&g_cursor[d.y], 1)] = s.y;
        g_csr_src[g_row_start[d.z] + atomicAdd(&g_cursor[d.z], 1)] = s.z;
        g_csr_src[g_row_start[d.w] + atomicAdd(&g_cursor[d.w], 1)] = s.w;
    } else {
        for (int e = base; e < N_EDGES; e++) {
            int v = dst[e];
            g_csr_src[g_row_start[v] + atomicAdd(&g_cursor[v], 1)] = src[e];
        }
    }
}

// ---------------- aggregation: persistent warps, dynamic node tickets ----------
__global__ __launch_bounds__(256)
void aggregate_kernel(float* __restrict__ out) {
    const int lane = threadIdx.x & 31;
    const int hh   = lane & 3;
    const int slot = lane >> 2;
    const int hg   = lane >> 3;

    while (true) {
        int base;
        if (lane == 0) base = atomicAdd(&g_node_ctr, 2);
        base = __shfl_sync(0xffffffffu, base, 0);
        if (base >= N_NODES) break;
        int vend = (base + 2 < N_NODES) ? base + 2 : N_NODES;

        for (int v = base; v < vend; v++) {
            int start = g_row_start[v];
            int end   = g_row_start[v + 1];

            // ---- pass 1: online softmax stats. 8 edge slots x 4 heads.
            float er_h = g_er[v * NH + hh];
            float m = -1e30f, ssum = 0.f;
            for (int e = start + slot; e < end; e += 8) {
                int s = g_csr_src[e];
                float x = g_el[s * NH + hh] + er_h;
                x = (x > 0.f) ? x : 0.2f * x;
                float mn = fmaxf(m, x);
                ssum = ssum * __expf(m - mn) + __expf(x - mn);
                m = mn;
            }
#pragma unroll
            for (int off = 4; off < 32; off <<= 1) {
                float m2 = __shfl_xor_sync(0xffffffffu, m, off);
                float s2 = __shfl_xor_sync(0xffffffffu, ssum, off);
                float mn = fmaxf(m, m2);
                ssum = ssum * __expf(m - mn) + s2 * __expf(m2 - mn);
                m = mn;
            }

            // ---- pass 2: weighted gather, unrolled x2. head = lane>>3.
            float m_g  = __shfl_sync(0xffffffffu, m, hg);
            float s_g  = __shfl_sync(0xffffffffu, ssum, hg);
            float er_g = __shfl_sync(0xffffffffu, er_h, hg);
            float inv = (s_g > 0.f) ? (1.0f / s_g) : 0.f;

            float acc[8];
#pragma unroll
            for (int k = 0; k < 8; k++) acc[k] = 0.f;

            int e = start;
            for (; e + 1 < end; e += 2) {
                int s0 = g_csr_src[e];
                int s1 = g_csr_src[e + 1];
                float x0 = g_el[s0 * NH + hg] + er_g;
                float x1 = g_el[s1 * NH + hg] + er_g;
                const float4* p0 = reinterpret_cast<const float4*>(g_ft + (long)s0 * HD + lane * 8);
                const float4* p1 = reinterpret_cast<const float4*>(g_ft + (long)s1 * HD + lane * 8);
                float4 a0 = p0[0], a1 = p0[1];
                float4 b0 = p1[0], b1 = p1[1];
                x0 = (x0 > 0.f) ? x0 : 0.2f * x0;
                x1 = (x1 > 0.f) ? x1 : 0.2f * x1;
                float w0 = __expf(x0 - m_g) * inv;
                float w1 = __expf(x1 - m_g) * inv;
                acc[0] = fmaf(w0, a0.x, acc[0]); acc[1] = fmaf(w0, a0.y, acc[1]);
                acc[2] = fmaf(w0, a0.z, acc[2]); acc[3] = fmaf(w0, a0.w, acc[3]);
                acc[4] = fmaf(w0, a1.x, acc[4]); acc[5] = fmaf(w0, a1.y, acc[5]);
                acc[6] = fmaf(w0, a1.z, acc[6]); acc[7] = fmaf(w0, a1.w, acc[7]);
                acc[0] = fmaf(w1, b0.x, acc[0]); acc[1] = fmaf(w1, b0.y, acc[1]);
                acc[2] = fmaf(w1, b0.z, acc[2]); acc[3] = fmaf(w1, b0.w, acc[3]);
                acc[4] = fmaf(w1, b1.x, acc[4]); acc[5] = fmaf(w1, b1.y, acc[5]);
                acc[6] = fmaf(w1, b1.z, acc[6]); acc[7] = fmaf(w1, b1.w, acc[7]);
            }
            if (e < end) {
                int s = g_csr_src[e];
                float x = g_el[s * NH + hg] + er_g;
                x = (x > 0.f) ? x : 0.2f * x;
                float wgt = __expf(x - m_g) * inv;
                const float4* p = reinterpret_cast<const float4*>(g_ft + (long)s * HD + lane * 8);
                float4 u0 = p[0], u1 = p[1];
                acc[0] = fmaf(wgt, u0.x, acc[0]); acc[1] = fmaf(wgt, u0.y, acc[1]);
                acc[2] = fmaf(wgt, u0.z, acc[2]); acc[3] = fmaf(wgt, u0.w, acc[3]);
                acc[4] = fmaf(wgt, u1.x, acc[4]); acc[5] = fmaf(wgt, u1.y, acc[5]);
                acc[6] = fmaf(wgt, u1.z, acc[6]); acc[7] = fmaf(wgt, u1.w, acc[7]);
            }
            float4* op = reinterpret_cast<float4*>(out + (long)v * HD + lane * 8);
            op[0] = make_float4(acc[0], acc[1], acc[2], acc[3]);
            op[1] = make_float4(acc[4], acc[5], acc[6], acc[7]);
        }
    }
}

// ---------------- launch ------------------------------------------------------
extern "C" void kernel_launch(void* const* d_in, const int* in_sizes, int n_in,
                              void* d_out, int out_size) {
    const float* feat = (const float*)d_in[0];
    const float* W    = (const float*)d_in[1];
    const float* al   = (const float*)d_in[2];
    const float* ar   = (const float*)d_in[3];
    const int*   src  = (const int*)d_in[4];
    const int*   dst  = (const int*)d_in[5];
    float* out = (float*)d_out;

    static int inited = 0;
    static cudaStream_t s2;
    static cudaEvent_t ev_fork, ev_join;
    if (!inited) {
        cudaFuncSetAttribute(mma_gemm_kernel,
                             cudaFuncAttributeMaxDynamicSharedMemorySize, GEMM_SMEM);
        cudaStreamCreateWithFlags(&s2, cudaStreamNonBlocking);
        cudaEventCreateWithFlags(&ev_fork, cudaEventDisableTiming);
        cudaEventCreateWithFlags(&ev_join, cudaEventDisableTiming);
        inited = 1;
    }

    // fork: CSR chain on s2, GEMM chain on the capture stream
    cudaEventRecord(ev_fork, 0);
    cudaStreamWaitEvent(s2, ev_fork, 0);

    // -- stream 0: projection path --
    wsplit_kernel<<<(IN_F * HD + 255) / 256, 256>>>(W);
    mma_gemm_kernel<<<(N_NODES + 63) / 64, 512, GEMM_SMEM>>>(feat, al, ar);

    // -- stream s2: CSR build path --
    zero_kernel<<<(N_NODES + 255) / 256, 256, 0, s2>>>();
    hist_kernel<<<(N_EDGES / 4 + 255) / 256, 256, 0, s2>>>(dst);
    scan1_kernel<<<SCAN_BLOCKS, 1024, 0, s2>>>();
    scan2_kernel<<<1, 64, 0, s2>>>();
    scan3_kernel<<<SCAN_BLOCKS, 1024, 0, s2>>>();
    scatter_kernel<<<(N_EDGES / 4 + 255) / 256, 256, 0, s2>>>(src, dst);

    // join
    cudaEventRecord(ev_join, s2);
    cudaStreamWaitEvent(0, ev_join, 0);

    aggregate_kernel<<<1184, 256>>>(out);
}